// round 7
// baseline (speedup 1.0000x reference)
#include <cuda_runtime.h>
#include <cstdint>

#define BATCH 4
#define NN 1024
#define LL 64
#define NP 256
#define IMG_PIX (BATCH * NN * NN)
#define KCHUNK 16                         // masks per chunk
#define NCHUNK (LL / KCHUNK)              // 4 chunks

// ---------------- scratch ----------------
__device__ float2 g_X[BATCH * NN * NN];                // 33.5MB
__device__ float2 g_S1[BATCH * KCHUNK * NP * NP];      // 33.5MB, reused per chunk AND as D
__device__ float  g_ACC[BATCH * NN * NN * 2];          // 33.5MB

// ---------------- complex helpers ----------------
__device__ __forceinline__ float2 cadd(float2 a, float2 b){ return make_float2(a.x+b.x, a.y+b.y); }
__device__ __forceinline__ float2 csub(float2 a, float2 b){ return make_float2(a.x-b.x, a.y-b.y); }
__device__ __forceinline__ float2 cmul(float2 a, float2 b){
    return make_float2(fmaf(a.x, b.x, -a.y*b.y), fmaf(a.x, b.y, a.y*b.x));
}

// ---------------- register DFT16 (verified) ----------------
template<int SGN>
__device__ __forceinline__ void dft16(float2* r) {
    const float C1 = 0.923879532511287f, S1 = 0.382683432365090f, C2 = 0.707106781186548f;
    const float2 W[8] = {
        {1.f, 0.f}, {C1, SGN*S1}, {C2, SGN*C2}, {S1, SGN*C1},
        {0.f, SGN*1.f}, {-S1, SGN*C1}, {-C2, SGN*C2}, {-C1, SGN*S1}
    };
    float2 t[16];
    #pragma unroll
    for (int j = 0; j < 8; ++j) {
        float2 a = r[j], b = r[j+8];
        t[2*j]   = cadd(a, b);
        t[2*j+1] = cmul(csub(a, b), W[j]);
    }
    #pragma unroll
    for (int j = 0; j < 8; ++j) {
        int off = j & ~1;
        float2 a = t[j], b = t[j+8];
        r[j+off]   = cadd(a, b);
        r[j+off+2] = cmul(csub(a, b), W[off]);
    }
    #pragma unroll
    for (int j = 0; j < 8; ++j) {
        int off = j & ~3;
        float2 a = r[j], b = r[j+8];
        t[j+off]   = cadd(a, b);
        t[j+off+4] = cmul(csub(a, b), W[off]);
    }
    #pragma unroll
    for (int j = 0; j < 8; ++j) {
        float2 a = t[j], b = t[j+8];
        r[j]   = cadd(a, b);
        r[j+8] = csub(a, b);
    }
}

// ---------------- register DFT32 (verified R6) ----------------
template<int SGN>
__device__ __forceinline__ void dft32(float2* r) {
    const float A1 = 0.980785280403230f, B1 = 0.195090322016128f;
    const float A2 = 0.923879532511287f, B2 = 0.382683432365090f;
    const float A3 = 0.831469612302545f, B3 = 0.555570233019602f;
    const float A4 = 0.707106781186548f;
    const float2 W[16] = {
        {1.f, 0.f},      {A1, SGN*B1},   {A2, SGN*B2},   {A3, SGN*B3},
        {A4, SGN*A4},    {B3, SGN*A3},   {B2, SGN*A2},   {B1, SGN*A1},
        {0.f, SGN*1.f},  {-B1, SGN*A1},  {-B2, SGN*A2},  {-B3, SGN*A3},
        {-A4, SGN*A4},   {-A3, SGN*B3},  {-A2, SGN*B2},  {-A1, SGN*B1}
    };
    float2 t[32];
    #pragma unroll
    for (int j = 0; j < 16; ++j) {
        float2 a = r[j], b = r[j+16];
        t[2*j]   = cadd(a, b);
        t[2*j+1] = cmul(csub(a, b), W[j]);
    }
    #pragma unroll
    for (int j = 0; j < 16; ++j) {
        int off = j & ~1;
        float2 a = t[j], b = t[j+16];
        r[j+off]   = cadd(a, b);
        r[j+off+2] = cmul(csub(a, b), W[off]);
    }
    #pragma unroll
    for (int j = 0; j < 16; ++j) {
        int off = j & ~3;
        float2 a = r[j], b = r[j+16];
        t[j+off]   = cadd(a, b);
        t[j+off+4] = cmul(csub(a, b), W[off]);
    }
    #pragma unroll
    for (int j = 0; j < 16; ++j) {
        int off = j & ~7;
        float2 a = t[j], b = t[j+16];
        r[j+off]   = cadd(a, b);
        r[j+off+8] = cmul(csub(a, b), W[off]);
    }
    #pragma unroll
    for (int j = 0; j < 16; ++j) {
        float2 a = r[j], b = r[j+16];
        t[j]    = cadd(a, b);
        t[j+16] = csub(a, b);
    }
    #pragma unroll
    for (int j = 0; j < 32; ++j) r[j] = t[j];
}

// ================= 1024-pt kernels (32x32 register four-step, verified R6) =================

__global__ __launch_bounds__(128) void k_rows_fwd_planar(const float* __restrict__ re, const float* __restrict__ im) {
    __shared__ float2 S[4 * 1056];
    int tid = threadIdx.x;
    int r = tid >> 5, t = tid & 31;
    int row = blockIdx.x * 4 + r;
    const float* rp = re + (size_t)row * NN;
    const float* ip = im + (size_t)row * NN;
    float2 x[32];
    #pragma unroll
    for (int m = 0; m < 32; ++m) x[m] = make_float2(rp[m*32 + t], ip[m*32 + t]);
    dft32<-1>(x);
    float ss, cc; sincospif(-(float)t / 512.0f, &ss, &cc);
    float2 wt = make_float2(cc, ss);
    float2 w  = make_float2(1.f, 0.f);
    float2* Sr = S + r * 1056;
    #pragma unroll
    for (int k1 = 0; k1 < 32; ++k1) {
        Sr[k1*33 + t] = cmul(x[k1], w);
        w = cmul(w, wt);
    }
    __syncthreads();
    float2 y[32];
    #pragma unroll
    for (int n2 = 0; n2 < 32; ++n2) y[n2] = Sr[t*33 + n2];
    dft32<-1>(y);
    float2* o = g_X + (size_t)row * NN;
    #pragma unroll
    for (int k2 = 0; k2 < 32; ++k2) o[t + 32*k2] = y[k2];
}

// rows_inv: reads ACC, RE-ZEROES it (replaces k_zero_acc), writes D into g_S1
__global__ __launch_bounds__(128) void k_rows_inv_acc() {
    __shared__ float2 S[4 * 1056];
    int tid = threadIdx.x;
    int r = tid >> 5, t = tid & 31;
    int row = blockIdx.x * 4 + r;
    float2* src = ((float2*)g_ACC) + (size_t)row * NN;
    float2 x[32];
    #pragma unroll
    for (int m = 0; m < 32; ++m) x[m] = src[m*32 + t];
    #pragma unroll
    for (int m = 0; m < 32; ++m) src[m*32 + t] = make_float2(0.f, 0.f);   // re-zero for next replay
    dft32<+1>(x);
    float ss, cc; sincospif((float)t / 512.0f, &ss, &cc);
    float2 wt = make_float2(cc, ss);
    float2 w  = make_float2(1.f, 0.f);
    float2* Sr = S + r * 1056;
    #pragma unroll
    for (int k1 = 0; k1 < 32; ++k1) {
        Sr[k1*33 + t] = cmul(x[k1], w);
        w = cmul(w, wt);
    }
    __syncthreads();
    float2 y[32];
    #pragma unroll
    for (int n2 = 0; n2 < 32; ++n2) y[n2] = Sr[t*33 + n2];
    dft32<+1>(y);
    float2* o = g_S1 + (size_t)row * NN;
    #pragma unroll
    for (int k2 = 0; k2 < 32; ++k2) o[t + 32*k2] = y[k2];
}

#define COLS_SMEM_BYTES (8 * 1058 * (int)sizeof(float2))

__global__ __launch_bounds__(256) void k_cols_fwd_X() {
    extern __shared__ float2 S[];
    int tid = threadIdx.x;
    int c = tid & 7, t = tid >> 3;
    int b  = blockIdx.x >> 7;
    int c0 = (blockIdx.x & 127) * 8;
    float2* img = g_X + (size_t)b * NN * NN;
    float2 x[32];
    #pragma unroll
    for (int m = 0; m < 32; ++m) x[m] = img[(size_t)(m*32 + t) * NN + c0 + c];
    dft32<-1>(x);
    float ss, cc; sincospif(-(float)t / 512.0f, &ss, &cc);
    float2 wt = make_float2(cc, ss);
    float2 w  = make_float2(1.f, 0.f);
    float2* Sc = S + c * 1058;
    #pragma unroll
    for (int k1 = 0; k1 < 32; ++k1) {
        Sc[k1*33 + t] = cmul(x[k1], w);
        w = cmul(w, wt);
    }
    __syncthreads();
    float2 y[32];
    #pragma unroll
    for (int n2 = 0; n2 < 32; ++n2) y[n2] = Sc[t*33 + n2];
    dft32<-1>(y);
    #pragma unroll
    for (int k2 = 0; k2 < 32; ++k2) img[(size_t)(t + 32*k2) * NN + c0 + c] = y[k2];
}

__global__ __launch_bounds__(256) void k_cols_inv_final(const float* __restrict__ img_a, const float* __restrict__ xre,
                                 const float* __restrict__ xim,  const float* __restrict__ lamb,
                                 const float* __restrict__ eta1, float* __restrict__ out,
                                 long long out_size) {
    extern __shared__ float2 S[];
    int tid = threadIdx.x;
    int c = tid & 7, t = tid >> 3;
    int b  = blockIdx.x >> 7;
    int c0 = (blockIdx.x & 127) * 8;
    const float2* img = g_S1 + (size_t)b * NN * NN;
    float2 x[32];
    #pragma unroll
    for (int m = 0; m < 32; ++m) x[m] = img[(size_t)(m*32 + t) * NN + c0 + c];
    dft32<+1>(x);
    float ss, cc; sincospif((float)t / 512.0f, &ss, &cc);
    float2 wt = make_float2(cc, ss);
    float2 w  = make_float2(1.f, 0.f);
    float2* Sc = S + c * 1058;
    #pragma unroll
    for (int k1 = 0; k1 < 32; ++k1) {
        Sc[k1*33 + t] = cmul(x[k1], w);
        w = cmul(w, wt);
    }
    __syncthreads();
    float2 y[32];
    #pragma unroll
    for (int n2 = 0; n2 < 32; ++n2) y[n2] = Sc[t*33 + n2];
    dft32<+1>(y);
    float e1  = eta1[0];
    float lm  = lamb[0];
    float bco = 100.0f * e1 * lm;
    float aco = 10.0f  * e1;
    float coef = aco / ((float)LL * 1048576.0f);
    float one_m_b = 1.0f - bco;
    #pragma unroll
    for (int k2 = 0; k2 < 32; ++k2) {
        int rrow = t + 32*k2;
        long long idx = ((long long)b * NN + rrow) * NN + c0 + c;
        float2 d = y[k2];
        float xr = xre[idx], xi = xim[idx];
        float m  = sqrtf(fmaf(xr, xr, xi * xi)) + 1e-6f;
        float fa = bco * img_a[idx] / m;
        float rcx = one_m_b * xr - coef * d.x + fa * xr;
        float rcy = one_m_b * xi - coef * d.y + fa * xi;
        if (idx < out_size) out[idx] = sqrtf(fmaf(rcx, rcx, rcy * rcy));
        long long ore = (long long)IMG_PIX + idx;
        long long oim = (long long)(2 * IMG_PIX) + idx;
        if (ore < out_size) out[ore] = rcx;
        if (oim < out_size) out[oim] = rcy;
    }
}

// ================= patch kernels (R5 verified math, chunked) =================
// chunk covers masks k in [kbase, kbase+16) for all batches.
// local patch index pk_local = b*KCHUNK + kk  in [0,64)

__global__ __launch_bounds__(256) void k_p1(const int* __restrict__ masks, const float* __restrict__ ctf, int kbase) {
    __shared__ float2 S[16 * 272];
    int tid = threadIdx.x;
    int r = tid >> 4, t = tid & 15;
    int rg = blockIdx.x & 15;
    int pkl = blockIdx.x >> 4;                 // 0..63
    int b  = pkl >> 4, kk = pkl & 15;
    int k  = kbase + kk;
    int mr = masks[2*k] - 1, mc = masks[2*k+1] - 1;
    int i  = (rg << 4) + r;
    int gr = (mr + i + 512) & 1023;
    const float2* Xrow = g_X + ((size_t)b * NN + gr) * NN;
    const float*  cfr  = ctf + i * NP;
    float2 x[16];
    #pragma unroll
    for (int m = 0; m < 16; ++m) {
        int j  = m*16 + t;
        int gc = (mc + j + 512) & 1023;
        float2 v = Xrow[gc];
        float cf = cfr[j];
        x[m] = make_float2(v.x * cf, v.y * cf);
    }
    dft16<+1>(x);
    float ss, cc; sincospif(2.0f * (float)t / 256.0f, &ss, &cc);
    float2 wt = make_float2(cc, ss);
    float2 w  = make_float2(1.f, 0.f);
    float2* Sr = S + r * 272;
    #pragma unroll
    for (int k1 = 0; k1 < 16; ++k1) {
        Sr[k1*17 + t] = cmul(x[k1], w);
        w = cmul(w, wt);
    }
    __syncthreads();
    float2 y[16];
    #pragma unroll
    for (int n2 = 0; n2 < 16; ++n2) y[n2] = Sr[t*17 + n2];
    dft16<+1>(y);
    float2* o = g_S1 + ((size_t)pkl * NP + i) * NP;
    #pragma unroll
    for (int k2 = 0; k2 < 16; ++k2) o[t + 16*k2] = y[k2];
}

__global__ __launch_bounds__(256) void k_p2(const float* __restrict__ Y, int kbase) {
    __shared__ float2 S[16 * 256];
    int tid = threadIdx.x;
    int t = tid >> 4, c = tid & 15;
    int pkl = blockIdx.x >> 4;
    int c0 = (blockIdx.x & 15) << 4;
    int b  = pkl >> 4, kk = pkl & 15;
    float2* P = g_S1 + (size_t)pkl * NP * NP;
    float2 x[16];
    #pragma unroll
    for (int m = 0; m < 16; ++m) x[m] = P[(m*16 + t) * NP + c0 + c];
    dft16<+1>(x);
    {
        float ss, cc; sincospif(2.0f * (float)t / 256.0f, &ss, &cc);
        float2 wt = make_float2(cc, ss);
        float2 w  = make_float2(1.f, 0.f);
        #pragma unroll
        for (int k1 = 0; k1 < 16; ++k1) {
            S[k1*256 + t*16 + c] = cmul(x[k1], w);
            w = cmul(w, wt);
        }
    }
    __syncthreads();
    float2 y[16];
    #pragma unroll
    for (int n2 = 0; n2 < 16; ++n2) y[n2] = S[t*256 + n2*16 + c];
    dft16<+1>(y);
    const float* Yp = Y + ((size_t)(b * LL + kbase + kk)) * NP * NP;
    const float inv = 1.0f / 65536.0f;
    #pragma unroll
    for (int k2 = 0; k2 < 16; ++k2) {
        float2 wv = make_float2(y[k2].x * inv, y[k2].y * inv);
        float mag = sqrtf(fmaf(wv.x, wv.x, wv.y * wv.y));
        float sy  = sqrtf(Yp[(t + 16*k2) * NP + c0 + c]);
        if (mag > 0.0f) {
            float f = 1.0f - sy / mag;
            y[k2] = make_float2(wv.x * f, wv.y * f);
        } else {
            y[k2] = make_float2(-sy, 0.0f);
        }
    }
    dft16<-1>(y);
    __syncthreads();
    {
        float ss, cc; sincospif(-2.0f * (float)t / 256.0f, &ss, &cc);
        float2 wt = make_float2(cc, ss);
        float2 w  = make_float2(1.f, 0.f);
        #pragma unroll
        for (int k1 = 0; k1 < 16; ++k1) {
            S[k1*256 + t*16 + c] = cmul(y[k1], w);
            w = cmul(w, wt);
        }
    }
    __syncthreads();
    float2 z[16];
    #pragma unroll
    for (int n2 = 0; n2 < 16; ++n2) z[n2] = S[t*256 + n2*16 + c];
    dft16<-1>(z);
    #pragma unroll
    for (int k2 = 0; k2 < 16; ++k2) P[(t + 16*k2) * NP + c0 + c] = z[k2];
}

__global__ __launch_bounds__(256) void k_p3(const int* __restrict__ masks, const float* __restrict__ ctf, int kbase) {
    __shared__ float2 S[16 * 272];
    int tid = threadIdx.x;
    int r = tid >> 4, t = tid & 15;
    int rg = blockIdx.x & 15;
    int pkl = blockIdx.x >> 4;
    int b  = pkl >> 4, kk = pkl & 15;
    int k  = kbase + kk;
    int mr = masks[2*k] - 1, mc = masks[2*k+1] - 1;
    int i  = (rg << 4) + r;
    const float2* src = g_S1 + ((size_t)pkl * NP + i) * NP;
    float2 x[16];
    #pragma unroll
    for (int m = 0; m < 16; ++m) x[m] = src[m*16 + t];
    dft16<-1>(x);
    float ss, cc; sincospif(-2.0f * (float)t / 256.0f, &ss, &cc);
    float2 wt = make_float2(cc, ss);
    float2 w  = make_float2(1.f, 0.f);
    float2* Sr = S + r * 272;
    #pragma unroll
    for (int k1 = 0; k1 < 16; ++k1) {
        Sr[k1*17 + t] = cmul(x[k1], w);
        w = cmul(w, wt);
    }
    __syncthreads();
    float2 y[16];
    #pragma unroll
    for (int n2 = 0; n2 < 16; ++n2) y[n2] = Sr[t*17 + n2];
    dft16<-1>(y);
    int gr = (mr + i + 512) & 1023;
    float* accrow = g_ACC + ((size_t)b * NN + gr) * NN * 2;
    const float* cfr = ctf + i * NP;
    #pragma unroll
    for (int k2 = 0; k2 < 16; ++k2) {
        int j  = t + 16*k2;
        float cf = cfr[j];
        int gc = (mc + j + 512) & 1023;
        atomicAdd(accrow + gc*2,     y[k2].x * cf);
        atomicAdd(accrow + gc*2 + 1, y[k2].y * cf);
    }
}

// ---------------- launch ----------------
extern "C" void kernel_launch(void* const* d_in, const int* in_sizes, int n_in,
                              void* d_out, int out_size) {
    const float* Img_a = (const float*)d_in[0];
    const float* Xre   = (const float*)d_in[1];
    const float* Xim   = (const float*)d_in[2];
    const float* Y     = (const float*)d_in[3];
    const int*   Masks = (const int*)  d_in[4];
    const float* CTF   = (const float*)d_in[5];
    const float* lamb  = (const float*)d_in[6];
    const float* eta1  = (const float*)d_in[7];
    float* out = (float*)d_out;

    cudaFuncSetAttribute((const void*)k_cols_fwd_X,
                         cudaFuncAttributeMaxDynamicSharedMemorySize, COLS_SMEM_BYTES);
    cudaFuncSetAttribute((const void*)k_cols_inv_final,
                         cudaFuncAttributeMaxDynamicSharedMemorySize, COLS_SMEM_BYTES);

    k_rows_fwd_planar<<<BATCH * NN / 4, 128>>>(Xre, Xim);
    k_cols_fwd_X<<<BATCH * 128, 256, COLS_SMEM_BYTES>>>();
    // patch pipeline in L2-resident chunks (scratch g_S1 reused each chunk)
    for (int cband = 0; cband < NCHUNK; ++cband) {
        int kbase = cband * KCHUNK;
        k_p1<<<BATCH * KCHUNK * 16, 256>>>(Masks, CTF, kbase);
        k_p2<<<BATCH * KCHUNK * 16, 256>>>(Y, kbase);
        k_p3<<<BATCH * KCHUNK * 16, 256>>>(Masks, CTF, kbase);
    }
    // rows_inv also re-zeroes ACC (replaces k_zero_acc)
    k_rows_inv_acc<<<BATCH * NN / 4, 128>>>();
    k_cols_inv_final<<<BATCH * 128, 256, COLS_SMEM_BYTES>>>(
        Img_a, Xre, Xim, lamb, eta1, out, (long long)out_size);
}

// round 8
// speedup vs baseline: 1.0684x; 1.0684x over previous
#include <cuda_runtime.h>
#include <cstdint>

#define BATCH 4
#define NN 1024
#define LL 64
#define NP 256
#define IMG_PIX (BATCH * NN * NN)

// ---------------- scratch ----------------
__device__ float2 g_X[BATCH * NN * NN];
__device__ float2 g_S1[BATCH * LL * NP * NP];
__device__ float  g_ACC[BATCH * NN * NN * 2];

// ---------------- complex helpers ----------------
__device__ __forceinline__ float2 cadd(float2 a, float2 b){ return make_float2(a.x+b.x, a.y+b.y); }
__device__ __forceinline__ float2 csub(float2 a, float2 b){ return make_float2(a.x-b.x, a.y-b.y); }
__device__ __forceinline__ float2 cmul(float2 a, float2 b){
    return make_float2(fmaf(a.x, b.x, -a.y*b.y), fmaf(a.x, b.y, a.y*b.x));
}
__device__ __forceinline__ float2 conjf2(float2 a){ return make_float2(a.x, -a.y); }

// ---------------- register DFT16 (verified) ----------------
template<int SGN>
__device__ __forceinline__ void dft16(float2* r) {
    const float C1 = 0.923879532511287f, S1 = 0.382683432365090f, C2 = 0.707106781186548f;
    const float2 W[8] = {
        {1.f, 0.f}, {C1, SGN*S1}, {C2, SGN*C2}, {S1, SGN*C1},
        {0.f, SGN*1.f}, {-S1, SGN*C1}, {-C2, SGN*C2}, {-C1, SGN*S1}
    };
    float2 t[16];
    #pragma unroll
    for (int j = 0; j < 8; ++j) {
        float2 a = r[j], b = r[j+8];
        t[2*j]   = cadd(a, b);
        t[2*j+1] = cmul(csub(a, b), W[j]);
    }
    #pragma unroll
    for (int j = 0; j < 8; ++j) {
        int off = j & ~1;
        float2 a = t[j], b = t[j+8];
        r[j+off]   = cadd(a, b);
        r[j+off+2] = cmul(csub(a, b), W[off]);
    }
    #pragma unroll
    for (int j = 0; j < 8; ++j) {
        int off = j & ~3;
        float2 a = r[j], b = r[j+8];
        t[j+off]   = cadd(a, b);
        t[j+off+4] = cmul(csub(a, b), W[off]);
    }
    #pragma unroll
    for (int j = 0; j < 8; ++j) {
        float2 a = t[j], b = t[j+8];
        r[j]   = cadd(a, b);
        r[j+8] = csub(a, b);
    }
}

// ---------------- register DFT32 (verified R6) ----------------
template<int SGN>
__device__ __forceinline__ void dft32(float2* r) {
    const float A1 = 0.980785280403230f, B1 = 0.195090322016128f;
    const float A2 = 0.923879532511287f, B2 = 0.382683432365090f;
    const float A3 = 0.831469612302545f, B3 = 0.555570233019602f;
    const float A4 = 0.707106781186548f;
    const float2 W[16] = {
        {1.f, 0.f},      {A1, SGN*B1},   {A2, SGN*B2},   {A3, SGN*B3},
        {A4, SGN*A4},    {B3, SGN*A3},   {B2, SGN*A2},   {B1, SGN*A1},
        {0.f, SGN*1.f},  {-B1, SGN*A1},  {-B2, SGN*A2},  {-B3, SGN*A3},
        {-A4, SGN*A4},   {-A3, SGN*B3},  {-A2, SGN*B2},  {-A1, SGN*B1}
    };
    float2 t[32];
    #pragma unroll
    for (int j = 0; j < 16; ++j) {
        float2 a = r[j], b = r[j+16];
        t[2*j]   = cadd(a, b);
        t[2*j+1] = cmul(csub(a, b), W[j]);
    }
    #pragma unroll
    for (int j = 0; j < 16; ++j) {
        int off = j & ~1;
        float2 a = t[j], b = t[j+16];
        r[j+off]   = cadd(a, b);
        r[j+off+2] = cmul(csub(a, b), W[off]);
    }
    #pragma unroll
    for (int j = 0; j < 16; ++j) {
        int off = j & ~3;
        float2 a = r[j], b = r[j+16];
        t[j+off]   = cadd(a, b);
        t[j+off+4] = cmul(csub(a, b), W[off]);
    }
    #pragma unroll
    for (int j = 0; j < 16; ++j) {
        int off = j & ~7;
        float2 a = t[j], b = t[j+16];
        r[j+off]   = cadd(a, b);
        r[j+off+8] = cmul(csub(a, b), W[off]);
    }
    #pragma unroll
    for (int j = 0; j < 16; ++j) {
        float2 a = r[j], b = r[j+16];
        t[j]    = cadd(a, b);
        t[j+16] = csub(a, b);
    }
    #pragma unroll
    for (int j = 0; j < 32; ++j) r[j] = t[j];
}

// Apply twiddles w^k1 (k1=0..15) to x[] and store to S with stride ST.
// 4 independent chains of depth 3 instead of one chain of 16.
__device__ __forceinline__ void tw_store16(float2* S, int ST, int t, const float2* x, float2 w1) {
    float2 w2 = cmul(w1, w1);
    float2 w4 = cmul(w2, w2);
    float2 w8 = cmul(w4, w4);
    float2 wA = make_float2(1.f, 0.f), wB = w4, wC = w8, wD = cmul(w8, w4);
    #pragma unroll
    for (int b = 0; b < 4; ++b) {
        S[(b)     * ST + t] = (b == 0) ? x[0] : cmul(x[b],      wA);
        S[(b + 4) * ST + t] = cmul(x[b + 4],  wB);
        S[(b + 8) * ST + t] = cmul(x[b + 8],  wC);
        S[(b + 12)* ST + t] = cmul(x[b + 12], wD);
        if (b == 0) wA = w1; else wA = cmul(wA, w1);
        wB = cmul(wB, w1);
        wC = cmul(wC, w1);
        wD = cmul(wD, w1);
    }
}

// Same for 32: 4 chains of depth 7.
__device__ __forceinline__ void tw_store32(float2* S, int ST, int t, const float2* x, float2 w1) {
    float2 w2  = cmul(w1, w1);
    float2 w4  = cmul(w2, w2);
    float2 w8  = cmul(w4, w4);
    float2 w16 = cmul(w8, w8);
    float2 wA = make_float2(1.f, 0.f), wB = w8, wC = w16, wD = cmul(w16, w8);
    #pragma unroll
    for (int b = 0; b < 8; ++b) {
        S[(b)      * ST + t] = (b == 0) ? x[0] : cmul(x[b],       wA);
        S[(b + 8)  * ST + t] = cmul(x[b + 8],   wB);
        S[(b + 16) * ST + t] = cmul(x[b + 16],  wC);
        S[(b + 24) * ST + t] = cmul(x[b + 24],  wD);
        if (b == 0) wA = w1; else wA = cmul(wA, w1);
        wB = cmul(wB, w1);
        wC = cmul(wC, w1);
        wD = cmul(wD, w1);
    }
}

// p2 variant: contiguous layout S[k1*256 + t*16 + c]
__device__ __forceinline__ void tw_store16_p2(float2* S, int t, int c, const float2* x, float2 w1) {
    float2 w2 = cmul(w1, w1);
    float2 w4 = cmul(w2, w2);
    float2 w8 = cmul(w4, w4);
    float2 wA = make_float2(1.f, 0.f), wB = w4, wC = w8, wD = cmul(w8, w4);
    int base = t*16 + c;
    #pragma unroll
    for (int b = 0; b < 4; ++b) {
        S[(b)     * 256 + base] = (b == 0) ? x[0] : cmul(x[b],      wA);
        S[(b + 4) * 256 + base] = cmul(x[b + 4],  wB);
        S[(b + 8) * 256 + base] = cmul(x[b + 8],  wC);
        S[(b + 12)* 256 + base] = cmul(x[b + 12], wD);
        if (b == 0) wA = w1; else wA = cmul(wA, w1);
        wB = cmul(wB, w1);
        wC = cmul(wC, w1);
        wD = cmul(wD, w1);
    }
}

// ================= 1024-pt kernels (32x32 register four-step) =================

__global__ __launch_bounds__(128) void k_rows_fwd_planar(const float* __restrict__ re, const float* __restrict__ im) {
    __shared__ float2 S[4 * 1056];
    int tid = threadIdx.x;
    int r = tid >> 5, t = tid & 31;
    int row = blockIdx.x * 4 + r;
    const float* rp = re + (size_t)row * NN;
    const float* ip = im + (size_t)row * NN;
    float2 x[32];
    #pragma unroll
    for (int m = 0; m < 32; ++m) x[m] = make_float2(rp[m*32 + t], ip[m*32 + t]);
    dft32<-1>(x);
    float ss, cc; sincospif(-(float)t / 512.0f, &ss, &cc);
    tw_store32(S + r * 1056, 33, t, x, make_float2(cc, ss));
    __syncthreads();
    float2 y[32];
    float2* Sr = S + r * 1056;
    #pragma unroll
    for (int n2 = 0; n2 < 32; ++n2) y[n2] = Sr[t*33 + n2];
    dft32<-1>(y);
    float2* o = g_X + (size_t)row * NN;
    #pragma unroll
    for (int k2 = 0; k2 < 32; ++k2) o[t + 32*k2] = y[k2];
}

// rows_inv: reads ACC, re-zeroes it, writes D into g_S1
__global__ __launch_bounds__(128) void k_rows_inv_acc() {
    __shared__ float2 S[4 * 1056];
    int tid = threadIdx.x;
    int r = tid >> 5, t = tid & 31;
    int row = blockIdx.x * 4 + r;
    float2* src = ((float2*)g_ACC) + (size_t)row * NN;
    float2 x[32];
    #pragma unroll
    for (int m = 0; m < 32; ++m) x[m] = src[m*32 + t];
    #pragma unroll
    for (int m = 0; m < 32; ++m) src[m*32 + t] = make_float2(0.f, 0.f);
    dft32<+1>(x);
    float ss, cc; sincospif((float)t / 512.0f, &ss, &cc);
    tw_store32(S + r * 1056, 33, t, x, make_float2(cc, ss));
    __syncthreads();
    float2 y[32];
    float2* Sr = S + r * 1056;
    #pragma unroll
    for (int n2 = 0; n2 < 32; ++n2) y[n2] = Sr[t*33 + n2];
    dft32<+1>(y);
    float2* o = g_S1 + (size_t)row * NN;
    #pragma unroll
    for (int k2 = 0; k2 < 32; ++k2) o[t + 32*k2] = y[k2];
}

#define COLS_SMEM_BYTES (8 * 1058 * (int)sizeof(float2))

__global__ __launch_bounds__(256) void k_cols_fwd_X() {
    extern __shared__ float2 S[];
    int tid = threadIdx.x;
    int c = tid & 7, t = tid >> 3;
    int b  = blockIdx.x >> 7;
    int c0 = (blockIdx.x & 127) * 8;
    float2* img = g_X + (size_t)b * NN * NN;
    float2 x[32];
    #pragma unroll
    for (int m = 0; m < 32; ++m) x[m] = img[(size_t)(m*32 + t) * NN + c0 + c];
    dft32<-1>(x);
    float ss, cc; sincospif(-(float)t / 512.0f, &ss, &cc);
    tw_store32(S + c * 1058, 33, t, x, make_float2(cc, ss));
    __syncthreads();
    float2 y[32];
    float2* Sc = S + c * 1058;
    #pragma unroll
    for (int n2 = 0; n2 < 32; ++n2) y[n2] = Sc[t*33 + n2];
    dft32<-1>(y);
    #pragma unroll
    for (int k2 = 0; k2 < 32; ++k2) img[(size_t)(t + 32*k2) * NN + c0 + c] = y[k2];
}

__global__ __launch_bounds__(256) void k_cols_inv_final(const float* __restrict__ img_a, const float* __restrict__ xre,
                                 const float* __restrict__ xim,  const float* __restrict__ lamb,
                                 const float* __restrict__ eta1, float* __restrict__ out,
                                 long long out_size) {
    extern __shared__ float2 S[];
    int tid = threadIdx.x;
    int c = tid & 7, t = tid >> 3;
    int b  = blockIdx.x >> 7;
    int c0 = (blockIdx.x & 127) * 8;
    const float2* img = g_S1 + (size_t)b * NN * NN;
    float2 x[32];
    #pragma unroll
    for (int m = 0; m < 32; ++m) x[m] = img[(size_t)(m*32 + t) * NN + c0 + c];
    dft32<+1>(x);
    float ss, cc; sincospif((float)t / 512.0f, &ss, &cc);
    tw_store32(S + c * 1058, 33, t, x, make_float2(cc, ss));
    __syncthreads();
    float2 y[32];
    float2* Sc = S + c * 1058;
    #pragma unroll
    for (int n2 = 0; n2 < 32; ++n2) y[n2] = Sc[t*33 + n2];
    dft32<+1>(y);
    float e1  = eta1[0];
    float lm  = lamb[0];
    float bco = 100.0f * e1 * lm;
    float aco = 10.0f  * e1;
    float coef = aco / ((float)LL * 1048576.0f);
    float one_m_b = 1.0f - bco;
    #pragma unroll
    for (int k2 = 0; k2 < 32; ++k2) {
        int rrow = t + 32*k2;
        long long idx = ((long long)b * NN + rrow) * NN + c0 + c;
        float2 d = y[k2];
        float xr = xre[idx], xi = xim[idx];
        float m  = sqrtf(fmaf(xr, xr, xi * xi)) + 1e-6f;
        float fa = bco * img_a[idx] / m;
        float rcx = one_m_b * xr - coef * d.x + fa * xr;
        float rcy = one_m_b * xi - coef * d.y + fa * xi;
        if (idx < out_size) out[idx] = sqrtf(fmaf(rcx, rcx, rcy * rcy));
        long long ore = (long long)IMG_PIX + idx;
        long long oim = (long long)(2 * IMG_PIX) + idx;
        if (ore < out_size) out[ore] = rcx;
        if (oim < out_size) out[oim] = rcy;
    }
}

// ================= patch kernels =================

__global__ __launch_bounds__(256) void k_p1(const int* __restrict__ masks, const float* __restrict__ ctf) {
    __shared__ float2 S[16 * 272];
    int tid = threadIdx.x;
    int r = tid >> 4, t = tid & 15;
    int rg = blockIdx.x & 15;
    int pk = blockIdx.x >> 4;
    int b  = pk >> 6, k = pk & 63;
    int mr = masks[2*k] - 1, mc = masks[2*k+1] - 1;
    int i  = (rg << 4) + r;
    int gr = (mr + i + 512) & 1023;
    const float2* Xrow = g_X + ((size_t)b * NN + gr) * NN;
    const float*  cfr  = ctf + i * NP;
    float2 x[16];
    #pragma unroll
    for (int m = 0; m < 16; ++m) {
        int j  = m*16 + t;
        int gc = (mc + j + 512) & 1023;
        float2 v = Xrow[gc];
        float cf = cfr[j];
        x[m] = make_float2(v.x * cf, v.y * cf);
    }
    dft16<+1>(x);
    float ss, cc; sincospif(2.0f * (float)t / 256.0f, &ss, &cc);
    tw_store16(S + r * 272, 17, t, x, make_float2(cc, ss));
    __syncthreads();
    float2 y[16];
    float2* Sr = S + r * 272;
    #pragma unroll
    for (int n2 = 0; n2 < 16; ++n2) y[n2] = Sr[t*17 + n2];
    dft16<+1>(y);
    float2* o = g_S1 + ((size_t)pk * NP + i) * NP;
    #pragma unroll
    for (int k2 = 0; k2 < 16; ++k2) o[t + 16*k2] = y[k2];
}

__global__ __launch_bounds__(256) void k_p2(const float* __restrict__ Y) {
    __shared__ float2 S[16 * 256];
    int tid = threadIdx.x;
    int t = tid >> 4, c = tid & 15;
    int pk = blockIdx.x >> 4;
    int c0 = (blockIdx.x & 15) << 4;
    float2* P = g_S1 + (size_t)pk * NP * NP;
    float2 x[16];
    #pragma unroll
    for (int m = 0; m < 16; ++m) x[m] = P[(m*16 + t) * NP + c0 + c];
    dft16<+1>(x);
    float ss, cc; sincospif(2.0f * (float)t / 256.0f, &ss, &cc);
    float2 w1inv = make_float2(cc, ss);
    tw_store16_p2(S, t, c, x, w1inv);
    __syncthreads();
    float2 y[16];
    #pragma unroll
    for (int n2 = 0; n2 < 16; ++n2) y[n2] = S[t*256 + n2*16 + c];
    dft16<+1>(y);
    const float* Yp = Y + (size_t)pk * NP * NP;
    const float inv = 1.0f / 65536.0f;
    #pragma unroll
    for (int k2 = 0; k2 < 16; ++k2) {
        float2 wv = make_float2(y[k2].x * inv, y[k2].y * inv);
        float mag = sqrtf(fmaf(wv.x, wv.x, wv.y * wv.y));
        float sy  = sqrtf(Yp[(t + 16*k2) * NP + c0 + c]);
        if (mag > 0.0f) {
            float f = 1.0f - sy / mag;
            y[k2] = make_float2(wv.x * f, wv.y * f);
        } else {
            y[k2] = make_float2(-sy, 0.0f);
        }
    }
    dft16<-1>(y);
    __syncthreads();
    tw_store16_p2(S, t, c, y, conjf2(w1inv));    // forward twiddle = conj(inverse)
    __syncthreads();
    float2 z[16];
    #pragma unroll
    for (int n2 = 0; n2 < 16; ++n2) z[n2] = S[t*256 + n2*16 + c];
    dft16<-1>(z);
    #pragma unroll
    for (int k2 = 0; k2 < 16; ++k2) P[(t + 16*k2) * NP + c0 + c] = z[k2];
}

__global__ __launch_bounds__(256) void k_p3(const int* __restrict__ masks, const float* __restrict__ ctf) {
    __shared__ float2 S[16 * 272];
    int tid = threadIdx.x;
    int r = tid >> 4, t = tid & 15;
    int rg = blockIdx.x & 15;
    int pk = blockIdx.x >> 4;
    int b  = pk >> 6, k = pk & 63;
    int mr = masks[2*k] - 1, mc = masks[2*k+1] - 1;
    int i  = (rg << 4) + r;
    const float2* src = g_S1 + ((size_t)pk * NP + i) * NP;
    float2 x[16];
    #pragma unroll
    for (int m = 0; m < 16; ++m) x[m] = src[m*16 + t];
    dft16<-1>(x);
    float ss, cc; sincospif(-2.0f * (float)t / 256.0f, &ss, &cc);
    tw_store16(S + r * 272, 17, t, x, make_float2(cc, ss));
    __syncthreads();
    float2 y[16];
    float2* Sr = S + r * 272;
    #pragma unroll
    for (int n2 = 0; n2 < 16; ++n2) y[n2] = Sr[t*17 + n2];
    dft16<-1>(y);
    int gr = (mr + i + 512) & 1023;
    float* accrow = g_ACC + ((size_t)b * NN + gr) * NN * 2;
    const float* cfr = ctf + i * NP;
    #pragma unroll
    for (int k2 = 0; k2 < 16; ++k2) {
        int j  = t + 16*k2;
        float cf = cfr[j];
        int gc = (mc + j + 512) & 1023;
        atomicAdd(accrow + gc*2,     y[k2].x * cf);
        atomicAdd(accrow + gc*2 + 1, y[k2].y * cf);
    }
}

// ---------------- launch ----------------
extern "C" void kernel_launch(void* const* d_in, const int* in_sizes, int n_in,
                              void* d_out, int out_size) {
    const float* Img_a = (const float*)d_in[0];
    const float* Xre   = (const float*)d_in[1];
    const float* Xim   = (const float*)d_in[2];
    const float* Y     = (const float*)d_in[3];
    const int*   Masks = (const int*)  d_in[4];
    const float* CTF   = (const float*)d_in[5];
    const float* lamb  = (const float*)d_in[6];
    const float* eta1  = (const float*)d_in[7];
    float* out = (float*)d_out;

    cudaFuncSetAttribute((const void*)k_cols_fwd_X,
                         cudaFuncAttributeMaxDynamicSharedMemorySize, COLS_SMEM_BYTES);
    cudaFuncSetAttribute((const void*)k_cols_inv_final,
                         cudaFuncAttributeMaxDynamicSharedMemorySize, COLS_SMEM_BYTES);

    k_rows_fwd_planar<<<BATCH * NN / 4, 128>>>(Xre, Xim);
    k_cols_fwd_X<<<BATCH * 128, 256, COLS_SMEM_BYTES>>>();
    k_p1<<<BATCH * LL * 16, 256>>>(Masks, CTF);
    k_p2<<<BATCH * LL * 16, 256>>>(Y);
    k_p3<<<BATCH * LL * 16, 256>>>(Masks, CTF);
    k_rows_inv_acc<<<BATCH * NN / 4, 128>>>();
    k_cols_inv_final<<<BATCH * 128, 256, COLS_SMEM_BYTES>>>(
        Img_a, Xre, Xim, lamb, eta1, out, (long long)out_size);
}

// round 10
// speedup vs baseline: 1.1733x; 1.0982x over previous
#include <cuda_runtime.h>
#include <cuda_fp16.h>
#include <cstdint>

#define BATCH 4
#define NN 1024
#define LL 64
#define NP 256
#define IMG_PIX (BATCH * NN * NN)

// ---------------- scratch ----------------
__device__ float2  g_X[BATCH * NN * NN];              // fp32 spectrum (33.5MB)
__device__ __half2 g_S1h[BATCH * LL * NP * NP];       // half2 patch scratch (67MB)
__device__ float   g_ACC[BATCH * NN * NN * 2];        // fp32 accumulator (33.5MB)
__device__ float2  g_D[BATCH * NN * NN];              // fp32 D intermediate (33.5MB)

// ---------------- complex helpers ----------------
__device__ __forceinline__ float2 cadd(float2 a, float2 b){ return make_float2(a.x+b.x, a.y+b.y); }
__device__ __forceinline__ float2 csub(float2 a, float2 b){ return make_float2(a.x-b.x, a.y-b.y); }
__device__ __forceinline__ float2 cmul(float2 a, float2 b){
    return make_float2(fmaf(a.x, b.x, -a.y*b.y), fmaf(a.x, b.y, a.y*b.x));
}
__device__ __forceinline__ float2 conjf2(float2 a){ return make_float2(a.x, -a.y); }
__device__ __forceinline__ __half2 f2h(float2 a){ return __floats2half2_rn(a.x, a.y); }
__device__ __forceinline__ float2 h2f(__half2 a){ float2 r = __half22float2(a); return r; }

// ---------------- register DFT16 (verified) ----------------
template<int SGN>
__device__ __forceinline__ void dft16(float2* r) {
    const float C1 = 0.923879532511287f, S1 = 0.382683432365090f, C2 = 0.707106781186548f;
    const float2 W[8] = {
        {1.f, 0.f}, {C1, SGN*S1}, {C2, SGN*C2}, {S1, SGN*C1},
        {0.f, SGN*1.f}, {-S1, SGN*C1}, {-C2, SGN*C2}, {-C1, SGN*S1}
    };
    float2 t[16];
    #pragma unroll
    for (int j = 0; j < 8; ++j) {
        float2 a = r[j], b = r[j+8];
        t[2*j]   = cadd(a, b);
        t[2*j+1] = cmul(csub(a, b), W[j]);
    }
    #pragma unroll
    for (int j = 0; j < 8; ++j) {
        int off = j & ~1;
        float2 a = t[j], b = t[j+8];
        r[j+off]   = cadd(a, b);
        r[j+off+2] = cmul(csub(a, b), W[off]);
    }
    #pragma unroll
    for (int j = 0; j < 8; ++j) {
        int off = j & ~3;
        float2 a = r[j], b = r[j+8];
        t[j+off]   = cadd(a, b);
        t[j+off+4] = cmul(csub(a, b), W[off]);
    }
    #pragma unroll
    for (int j = 0; j < 8; ++j) {
        float2 a = t[j], b = t[j+8];
        r[j]   = cadd(a, b);
        r[j+8] = csub(a, b);
    }
}

// ---------------- register DFT32 (verified R6) ----------------
template<int SGN>
__device__ __forceinline__ void dft32(float2* r) {
    const float A1 = 0.980785280403230f, B1 = 0.195090322016128f;
    const float A2 = 0.923879532511287f, B2 = 0.382683432365090f;
    const float A3 = 0.831469612302545f, B3 = 0.555570233019602f;
    const float A4 = 0.707106781186548f;
    const float2 W[16] = {
        {1.f, 0.f},      {A1, SGN*B1},   {A2, SGN*B2},   {A3, SGN*B3},
        {A4, SGN*A4},    {B3, SGN*A3},   {B2, SGN*A2},   {B1, SGN*A1},
        {0.f, SGN*1.f},  {-B1, SGN*A1},  {-B2, SGN*A2},  {-B3, SGN*A3},
        {-A4, SGN*A4},   {-A3, SGN*B3},  {-A2, SGN*B2},  {-A1, SGN*B1}
    };
    float2 t[32];
    #pragma unroll
    for (int j = 0; j < 16; ++j) {
        float2 a = r[j], b = r[j+16];
        t[2*j]   = cadd(a, b);
        t[2*j+1] = cmul(csub(a, b), W[j]);
    }
    #pragma unroll
    for (int j = 0; j < 16; ++j) {
        int off = j & ~1;
        float2 a = t[j], b = t[j+16];
        r[j+off]   = cadd(a, b);
        r[j+off+2] = cmul(csub(a, b), W[off]);
    }
    #pragma unroll
    for (int j = 0; j < 16; ++j) {
        int off = j & ~3;
        float2 a = r[j], b = r[j+16];
        t[j+off]   = cadd(a, b);
        t[j+off+4] = cmul(csub(a, b), W[off]);
    }
    #pragma unroll
    for (int j = 0; j < 16; ++j) {
        int off = j & ~7;
        float2 a = t[j], b = t[j+16];
        r[j+off]   = cadd(a, b);
        r[j+off+8] = cmul(csub(a, b), W[off]);
    }
    #pragma unroll
    for (int j = 0; j < 16; ++j) {
        float2 a = r[j], b = r[j+16];
        t[j]    = cadd(a, b);
        t[j+16] = csub(a, b);
    }
    #pragma unroll
    for (int j = 0; j < 32; ++j) r[j] = t[j];
}

// chain-split twiddle stores (verified R8)
__device__ __forceinline__ void tw_store16(float2* S, int ST, int t, const float2* x, float2 w1) {
    float2 w2 = cmul(w1, w1);
    float2 w4 = cmul(w2, w2);
    float2 w8 = cmul(w4, w4);
    float2 wA = make_float2(1.f, 0.f), wB = w4, wC = w8, wD = cmul(w8, w4);
    #pragma unroll
    for (int b = 0; b < 4; ++b) {
        S[(b)     * ST + t] = (b == 0) ? x[0] : cmul(x[b],      wA);
        S[(b + 4) * ST + t] = cmul(x[b + 4],  wB);
        S[(b + 8) * ST + t] = cmul(x[b + 8],  wC);
        S[(b + 12)* ST + t] = cmul(x[b + 12], wD);
        if (b == 0) wA = w1; else wA = cmul(wA, w1);
        wB = cmul(wB, w1);
        wC = cmul(wC, w1);
        wD = cmul(wD, w1);
    }
}

__device__ __forceinline__ void tw_store32(float2* S, int ST, int t, const float2* x, float2 w1) {
    float2 w2  = cmul(w1, w1);
    float2 w4  = cmul(w2, w2);
    float2 w8  = cmul(w4, w4);
    float2 w16 = cmul(w8, w8);
    float2 wA = make_float2(1.f, 0.f), wB = w8, wC = w16, wD = cmul(w16, w8);
    #pragma unroll
    for (int b = 0; b < 8; ++b) {
        S[(b)      * ST + t] = (b == 0) ? x[0] : cmul(x[b],       wA);
        S[(b + 8)  * ST + t] = cmul(x[b + 8],   wB);
        S[(b + 16) * ST + t] = cmul(x[b + 16],  wC);
        S[(b + 24) * ST + t] = cmul(x[b + 24],  wD);
        if (b == 0) wA = w1; else wA = cmul(wA, w1);
        wB = cmul(wB, w1);
        wC = cmul(wC, w1);
        wD = cmul(wD, w1);
    }
}

__device__ __forceinline__ void tw_store16_p2(float2* S, int t, int c, const float2* x, float2 w1) {
    float2 w2 = cmul(w1, w1);
    float2 w4 = cmul(w2, w2);
    float2 w8 = cmul(w4, w4);
    float2 wA = make_float2(1.f, 0.f), wB = w4, wC = w8, wD = cmul(w8, w4);
    int base = t*16 + c;
    #pragma unroll
    for (int b = 0; b < 4; ++b) {
        S[(b)     * 256 + base] = (b == 0) ? x[0] : cmul(x[b],      wA);
        S[(b + 4) * 256 + base] = cmul(x[b + 4],  wB);
        S[(b + 8) * 256 + base] = cmul(x[b + 8],  wC);
        S[(b + 12)* 256 + base] = cmul(x[b + 12], wD);
        if (b == 0) wA = w1; else wA = cmul(wA, w1);
        wB = cmul(wB, w1);
        wC = cmul(wC, w1);
        wD = cmul(wD, w1);
    }
}

// ================= 1024-pt kernels =================

__global__ __launch_bounds__(128) void k_rows_fwd_planar(const float* __restrict__ re, const float* __restrict__ im) {
    __shared__ float2 S[4 * 1056];
    int tid = threadIdx.x;
    int r = tid >> 5, t = tid & 31;
    int row = blockIdx.x * 4 + r;
    const float* rp = re + (size_t)row * NN;
    const float* ip = im + (size_t)row * NN;
    float2 x[32];
    #pragma unroll
    for (int m = 0; m < 32; ++m) x[m] = make_float2(rp[m*32 + t], ip[m*32 + t]);
    dft32<-1>(x);
    float ss, cc; sincospif(-(float)t / 512.0f, &ss, &cc);
    tw_store32(S + r * 1056, 33, t, x, make_float2(cc, ss));
    __syncthreads();
    float2 y[32];
    float2* Sr = S + r * 1056;
    #pragma unroll
    for (int n2 = 0; n2 < 32; ++n2) y[n2] = Sr[t*33 + n2];
    dft32<-1>(y);
    float2* o = g_X + (size_t)row * NN;
    #pragma unroll
    for (int k2 = 0; k2 < 32; ++k2) o[t + 32*k2] = y[k2];
}

// rows_inv: reads ACC, re-zeroes it, writes D into g_D (fp32)
__global__ __launch_bounds__(128) void k_rows_inv_acc() {
    __shared__ float2 S[4 * 1056];
    int tid = threadIdx.x;
    int r = tid >> 5, t = tid & 31;
    int row = blockIdx.x * 4 + r;
    float2* src = ((float2*)g_ACC) + (size_t)row * NN;
    float2 x[32];
    #pragma unroll
    for (int m = 0; m < 32; ++m) x[m] = src[m*32 + t];
    #pragma unroll
    for (int m = 0; m < 32; ++m) src[m*32 + t] = make_float2(0.f, 0.f);
    dft32<+1>(x);
    float ss, cc; sincospif((float)t / 512.0f, &ss, &cc);
    tw_store32(S + r * 1056, 33, t, x, make_float2(cc, ss));
    __syncthreads();
    float2 y[32];
    float2* Sr = S + r * 1056;
    #pragma unroll
    for (int n2 = 0; n2 < 32; ++n2) y[n2] = Sr[t*33 + n2];
    dft32<+1>(y);
    float2* o = g_D + (size_t)row * NN;
    #pragma unroll
    for (int k2 = 0; k2 < 32; ++k2) o[t + 32*k2] = y[k2];
}

#define COLS_SMEM_BYTES (8 * 1058 * (int)sizeof(float2))

__global__ __launch_bounds__(256) void k_cols_fwd_X() {
    extern __shared__ float2 S[];
    int tid = threadIdx.x;
    int c = tid & 7, t = tid >> 3;
    int b  = blockIdx.x >> 7;
    int c0 = (blockIdx.x & 127) * 8;
    float2* img = g_X + (size_t)b * NN * NN;
    float2 x[32];
    #pragma unroll
    for (int m = 0; m < 32; ++m) x[m] = img[(size_t)(m*32 + t) * NN + c0 + c];
    dft32<-1>(x);
    float ss, cc; sincospif(-(float)t / 512.0f, &ss, &cc);
    tw_store32(S + c * 1058, 33, t, x, make_float2(cc, ss));
    __syncthreads();
    float2 y[32];
    float2* Sc = S + c * 1058;
    #pragma unroll
    for (int n2 = 0; n2 < 32; ++n2) y[n2] = Sc[t*33 + n2];
    dft32<-1>(y);
    #pragma unroll
    for (int k2 = 0; k2 < 32; ++k2) img[(size_t)(t + 32*k2) * NN + c0 + c] = y[k2];
}

__global__ __launch_bounds__(256) void k_cols_inv_final(const float* __restrict__ img_a, const float* __restrict__ xre,
                                 const float* __restrict__ xim,  const float* __restrict__ lamb,
                                 const float* __restrict__ eta1, float* __restrict__ out,
                                 long long out_size) {
    extern __shared__ float2 S[];
    int tid = threadIdx.x;
    int c = tid & 7, t = tid >> 3;
    int b  = blockIdx.x >> 7;
    int c0 = (blockIdx.x & 127) * 8;
    const float2* img = g_D + (size_t)b * NN * NN;
    float2 x[32];
    #pragma unroll
    for (int m = 0; m < 32; ++m) x[m] = img[(size_t)(m*32 + t) * NN + c0 + c];
    dft32<+1>(x);
    float ss, cc; sincospif((float)t / 512.0f, &ss, &cc);
    tw_store32(S + c * 1058, 33, t, x, make_float2(cc, ss));
    __syncthreads();
    float2 y[32];
    float2* Sc = S + c * 1058;
    #pragma unroll
    for (int n2 = 0; n2 < 32; ++n2) y[n2] = Sc[t*33 + n2];
    dft32<+1>(y);
    float e1  = eta1[0];
    float lm  = lamb[0];
    float bco = 100.0f * e1 * lm;
    float aco = 10.0f  * e1;
    // Cz is stored at TRUE scale (Bz scale folding divides out in the projection),
    // so ACC/D are unchanged: full ifft2 norm + /L applies here.
    float coef = aco / ((float)LL * 1048576.0f);
    float one_m_b = 1.0f - bco;
    #pragma unroll
    for (int k2 = 0; k2 < 32; ++k2) {
        int rrow = t + 32*k2;
        long long idx = ((long long)b * NN + rrow) * NN + c0 + c;
        float2 d = y[k2];
        float xr = xre[idx], xi = xim[idx];
        float m  = sqrtf(fmaf(xr, xr, xi * xi)) + 1e-6f;
        float fa = bco * img_a[idx] / m;
        float rcx = one_m_b * xr - coef * d.x + fa * xr;
        float rcy = one_m_b * xi - coef * d.y + fa * xi;
        if (idx < out_size) out[idx] = sqrtf(fmaf(rcx, rcx, rcy * rcy));
        long long ore = (long long)IMG_PIX + idx;
        long long oim = (long long)(2 * IMG_PIX) + idx;
        if (ore < out_size) out[ore] = rcx;
        if (oim < out_size) out[oim] = rcy;
    }
}

// ================= patch kernels (half2 intermediates) =================

__global__ __launch_bounds__(256) void k_p1(const int* __restrict__ masks, const float* __restrict__ ctf) {
    __shared__ float2 S[16 * 272];
    int tid = threadIdx.x;
    int r = tid >> 4, t = tid & 15;
    int rg = blockIdx.x & 15;
    int pk = blockIdx.x >> 4;
    int b  = pk >> 6, k = pk & 63;
    int mr = masks[2*k] - 1, mc = masks[2*k+1] - 1;
    int i  = (rg << 4) + r;
    int gr = (mr + i + 512) & 1023;
    const float2* Xrow = g_X + ((size_t)b * NN + gr) * NN;
    const float*  cfr  = ctf + i * NP;
    float2 x[16];
    const float sc = 1.0f / 256.0f;               // range-fold for half storage
    #pragma unroll
    for (int m = 0; m < 16; ++m) {
        int j  = m*16 + t;
        int gc = (mc + j + 512) & 1023;
        float2 v = Xrow[gc];
        float cf = cfr[j] * sc;
        x[m] = make_float2(v.x * cf, v.y * cf);
    }
    dft16<+1>(x);
    float ss, cc; sincospif(2.0f * (float)t / 256.0f, &ss, &cc);
    tw_store16(S + r * 272, 17, t, x, make_float2(cc, ss));
    __syncthreads();
    float2 y[16];
    float2* Sr = S + r * 272;
    #pragma unroll
    for (int n2 = 0; n2 < 16; ++n2) y[n2] = Sr[t*17 + n2];
    dft16<+1>(y);
    __half2* o = g_S1h + ((size_t)pk * NP + i) * NP;
    #pragma unroll
    for (int k2 = 0; k2 < 16; ++k2) o[t + 16*k2] = f2h(y[k2]);
}

__global__ __launch_bounds__(256) void k_p2(const float* __restrict__ Y) {
    __shared__ float2 S[16 * 256];
    int tid = threadIdx.x;
    int t = tid >> 4, c = tid & 15;
    int pk = blockIdx.x >> 4;
    int c0 = (blockIdx.x & 15) << 4;
    __half2* P = g_S1h + (size_t)pk * NP * NP;
    float2 x[16];
    #pragma unroll
    for (int m = 0; m < 16; ++m) x[m] = h2f(P[(m*16 + t) * NP + c0 + c]);
    dft16<+1>(x);
    float ss, cc; sincospif(2.0f * (float)t / 256.0f, &ss, &cc);
    float2 w1inv = make_float2(cc, ss);
    tw_store16_p2(S, t, c, x, w1inv);
    __syncthreads();
    float2 y[16];
    #pragma unroll
    for (int n2 = 0; n2 < 16; ++n2) y[n2] = S[t*256 + n2*16 + c];
    dft16<+1>(y);
    const float* Yp = Y + (size_t)pk * NP * NP;
    const float inv = 1.0f / 256.0f;             // remaining ifft2 norm (1/256 folded at p1)
    #pragma unroll
    for (int k2 = 0; k2 < 16; ++k2) {
        float2 wv = make_float2(y[k2].x * inv, y[k2].y * inv);
        float mag = sqrtf(fmaf(wv.x, wv.x, wv.y * wv.y));
        float sy  = sqrtf(Yp[(t + 16*k2) * NP + c0 + c]);
        if (mag > 0.0f) {
            float f = 1.0f - sy / mag;
            y[k2] = make_float2(wv.x * f, wv.y * f);
        } else {
            y[k2] = make_float2(-sy, 0.0f);
        }
    }
    dft16<-1>(y);
    __syncthreads();
    tw_store16_p2(S, t, c, y, conjf2(w1inv));
    __syncthreads();
    float2 z[16];
    #pragma unroll
    for (int n2 = 0; n2 < 16; ++n2) z[n2] = S[t*256 + n2*16 + c];
    dft16<-1>(z);
    #pragma unroll
    for (int k2 = 0; k2 < 16; ++k2) P[(t + 16*k2) * NP + c0 + c] = f2h(z[k2]);
}

__global__ __launch_bounds__(256) void k_p3(const int* __restrict__ masks, const float* __restrict__ ctf) {
    __shared__ float2 S[16 * 272];
    int tid = threadIdx.x;
    int r = tid >> 4, t = tid & 15;
    int rg = blockIdx.x & 15;
    int pk = blockIdx.x >> 4;
    int b  = pk >> 6, k = pk & 63;
    int mr = masks[2*k] - 1, mc = masks[2*k+1] - 1;
    int i  = (rg << 4) + r;
    const __half2* src = g_S1h + ((size_t)pk * NP + i) * NP;
    float2 x[16];
    #pragma unroll
    for (int m = 0; m < 16; ++m) x[m] = h2f(src[m*16 + t]);
    dft16<-1>(x);
    float ss, cc; sincospif(-2.0f * (float)t / 256.0f, &ss, &cc);
    tw_store16(S + r * 272, 17, t, x, make_float2(cc, ss));
    __syncthreads();
    float2 y[16];
    float2* Sr = S + r * 272;
    #pragma unroll
    for (int n2 = 0; n2 < 16; ++n2) y[n2] = Sr[t*17 + n2];
    dft16<-1>(y);
    int gr = (mr + i + 512) & 1023;
    float* accrow = g_ACC + ((size_t)b * NN + gr) * NN * 2;
    const float* cfr = ctf + i * NP;
    #pragma unroll
    for (int k2 = 0; k2 < 16; ++k2) {
        int j  = t + 16*k2;
        float cf = cfr[j];
        int gc = (mc + j + 512) & 1023;
        atomicAdd(accrow + gc*2,     y[k2].x * cf);
        atomicAdd(accrow + gc*2 + 1, y[k2].y * cf);
    }
}

// ---------------- launch ----------------
extern "C" void kernel_launch(void* const* d_in, const int* in_sizes, int n_in,
                              void* d_out, int out_size) {
    const float* Img_a = (const float*)d_in[0];
    const float* Xre   = (const float*)d_in[1];
    const float* Xim   = (const float*)d_in[2];
    const float* Y     = (const float*)d_in[3];
    const int*   Masks = (const int*)  d_in[4];
    const float* CTF   = (const float*)d_in[5];
    const float* lamb  = (const float*)d_in[6];
    const float* eta1  = (const float*)d_in[7];
    float* out = (float*)d_out;

    cudaFuncSetAttribute((const void*)k_cols_fwd_X,
                         cudaFuncAttributeMaxDynamicSharedMemorySize, COLS_SMEM_BYTES);
    cudaFuncSetAttribute((const void*)k_cols_inv_final,
                         cudaFuncAttributeMaxDynamicSharedMemorySize, COLS_SMEM_BYTES);

    k_rows_fwd_planar<<<BATCH * NN / 4, 128>>>(Xre, Xim);
    k_cols_fwd_X<<<BATCH * 128, 256, COLS_SMEM_BYTES>>>();
    k_p1<<<BATCH * LL * 16, 256>>>(Masks, CTF);
    k_p2<<<BATCH * LL * 16, 256>>>(Y);
    k_p3<<<BATCH * LL * 16, 256>>>(Masks, CTF);
    k_rows_inv_acc<<<BATCH * NN / 4, 128>>>();
    k_cols_inv_final<<<BATCH * 128, 256, COLS_SMEM_BYTES>>>(
        Img_a, Xre, Xim, lamb, eta1, out, (long long)out_size);
}

// round 11
// speedup vs baseline: 1.4129x; 1.2042x over previous
#include <cuda_runtime.h>
#include <cuda_fp16.h>
#include <cstdint>

#define BATCH 4
#define NN 1024
#define LL 64
#define NP 256
#define IMG_PIX (BATCH * NN * NN)

// ---------------- scratch ----------------
__device__ float2  g_X[BATCH * NN * NN];              // fp32 spectrum (33.5MB)
__device__ __half2 g_S1h[BATCH * LL * NP * NP];       // half2 patch scratch (67MB)
__device__ float   g_ACC[BATCH * NN * NN * 2];        // fp32 accumulator (33.5MB)
__device__ float2  g_D[BATCH * NN * NN];              // fp32 D intermediate (33.5MB)

// ---------------- complex helpers ----------------
__device__ __forceinline__ float2 cadd(float2 a, float2 b){ return make_float2(a.x+b.x, a.y+b.y); }
__device__ __forceinline__ float2 csub(float2 a, float2 b){ return make_float2(a.x-b.x, a.y-b.y); }
__device__ __forceinline__ float2 cmul(float2 a, float2 b){
    return make_float2(fmaf(a.x, b.x, -a.y*b.y), fmaf(a.x, b.y, a.y*b.x));
}
__device__ __forceinline__ float2 conjf2(float2 a){ return make_float2(a.x, -a.y); }
__device__ __forceinline__ __half2 f2h(float2 a){ return __floats2half2_rn(a.x, a.y); }
__device__ __forceinline__ float2 h2f(__half2 a){ float2 r = __half22float2(a); return r; }

// packed float2 global reduction (sm_90+): one red op for (re,im)
__device__ __forceinline__ void red_add_v2(float* addr, float vx, float vy) {
    asm volatile("red.global.add.v2.f32 [%0], {%1, %2};"
                 :: "l"(addr), "f"(vx), "f"(vy) : "memory");
}

// ---------------- register DFT16 (verified) ----------------
template<int SGN>
__device__ __forceinline__ void dft16(float2* r) {
    const float C1 = 0.923879532511287f, S1 = 0.382683432365090f, C2 = 0.707106781186548f;
    const float2 W[8] = {
        {1.f, 0.f}, {C1, SGN*S1}, {C2, SGN*C2}, {S1, SGN*C1},
        {0.f, SGN*1.f}, {-S1, SGN*C1}, {-C2, SGN*C2}, {-C1, SGN*S1}
    };
    float2 t[16];
    #pragma unroll
    for (int j = 0; j < 8; ++j) {
        float2 a = r[j], b = r[j+8];
        t[2*j]   = cadd(a, b);
        t[2*j+1] = cmul(csub(a, b), W[j]);
    }
    #pragma unroll
    for (int j = 0; j < 8; ++j) {
        int off = j & ~1;
        float2 a = t[j], b = t[j+8];
        r[j+off]   = cadd(a, b);
        r[j+off+2] = cmul(csub(a, b), W[off]);
    }
    #pragma unroll
    for (int j = 0; j < 8; ++j) {
        int off = j & ~3;
        float2 a = r[j], b = r[j+8];
        t[j+off]   = cadd(a, b);
        t[j+off+4] = cmul(csub(a, b), W[off]);
    }
    #pragma unroll
    for (int j = 0; j < 8; ++j) {
        float2 a = t[j], b = t[j+8];
        r[j]   = cadd(a, b);
        r[j+8] = csub(a, b);
    }
}

// ---------------- register DFT32 (verified R6) ----------------
template<int SGN>
__device__ __forceinline__ void dft32(float2* r) {
    const float A1 = 0.980785280403230f, B1 = 0.195090322016128f;
    const float A2 = 0.923879532511287f, B2 = 0.382683432365090f;
    const float A3 = 0.831469612302545f, B3 = 0.555570233019602f;
    const float A4 = 0.707106781186548f;
    const float2 W[16] = {
        {1.f, 0.f},      {A1, SGN*B1},   {A2, SGN*B2},   {A3, SGN*B3},
        {A4, SGN*A4},    {B3, SGN*A3},   {B2, SGN*A2},   {B1, SGN*A1},
        {0.f, SGN*1.f},  {-B1, SGN*A1},  {-B2, SGN*A2},  {-B3, SGN*A3},
        {-A4, SGN*A4},   {-A3, SGN*B3},  {-A2, SGN*B2},  {-A1, SGN*B1}
    };
    float2 t[32];
    #pragma unroll
    for (int j = 0; j < 16; ++j) {
        float2 a = r[j], b = r[j+16];
        t[2*j]   = cadd(a, b);
        t[2*j+1] = cmul(csub(a, b), W[j]);
    }
    #pragma unroll
    for (int j = 0; j < 16; ++j) {
        int off = j & ~1;
        float2 a = t[j], b = t[j+16];
        r[j+off]   = cadd(a, b);
        r[j+off+2] = cmul(csub(a, b), W[off]);
    }
    #pragma unroll
    for (int j = 0; j < 16; ++j) {
        int off = j & ~3;
        float2 a = r[j], b = r[j+16];
        t[j+off]   = cadd(a, b);
        t[j+off+4] = cmul(csub(a, b), W[off]);
    }
    #pragma unroll
    for (int j = 0; j < 16; ++j) {
        int off = j & ~7;
        float2 a = t[j], b = t[j+16];
        r[j+off]   = cadd(a, b);
        r[j+off+8] = cmul(csub(a, b), W[off]);
    }
    #pragma unroll
    for (int j = 0; j < 16; ++j) {
        float2 a = r[j], b = r[j+16];
        t[j]    = cadd(a, b);
        t[j+16] = csub(a, b);
    }
    #pragma unroll
    for (int j = 0; j < 32; ++j) r[j] = t[j];
}

// chain-split twiddle stores (verified R8)
__device__ __forceinline__ void tw_store16(float2* S, int ST, int t, const float2* x, float2 w1) {
    float2 w2 = cmul(w1, w1);
    float2 w4 = cmul(w2, w2);
    float2 w8 = cmul(w4, w4);
    float2 wA = make_float2(1.f, 0.f), wB = w4, wC = w8, wD = cmul(w8, w4);
    #pragma unroll
    for (int b = 0; b < 4; ++b) {
        S[(b)     * ST + t] = (b == 0) ? x[0] : cmul(x[b],      wA);
        S[(b + 4) * ST + t] = cmul(x[b + 4],  wB);
        S[(b + 8) * ST + t] = cmul(x[b + 8],  wC);
        S[(b + 12)* ST + t] = cmul(x[b + 12], wD);
        if (b == 0) wA = w1; else wA = cmul(wA, w1);
        wB = cmul(wB, w1);
        wC = cmul(wC, w1);
        wD = cmul(wD, w1);
    }
}

__device__ __forceinline__ void tw_store32(float2* S, int ST, int t, const float2* x, float2 w1) {
    float2 w2  = cmul(w1, w1);
    float2 w4  = cmul(w2, w2);
    float2 w8  = cmul(w4, w4);
    float2 w16 = cmul(w8, w8);
    float2 wA = make_float2(1.f, 0.f), wB = w8, wC = w16, wD = cmul(w16, w8);
    #pragma unroll
    for (int b = 0; b < 8; ++b) {
        S[(b)      * ST + t] = (b == 0) ? x[0] : cmul(x[b],       wA);
        S[(b + 8)  * ST + t] = cmul(x[b + 8],   wB);
        S[(b + 16) * ST + t] = cmul(x[b + 16],  wC);
        S[(b + 24) * ST + t] = cmul(x[b + 24],  wD);
        if (b == 0) wA = w1; else wA = cmul(wA, w1);
        wB = cmul(wB, w1);
        wC = cmul(wC, w1);
        wD = cmul(wD, w1);
    }
}

__device__ __forceinline__ void tw_store16_p2(float2* S, int t, int c, const float2* x, float2 w1) {
    float2 w2 = cmul(w1, w1);
    float2 w4 = cmul(w2, w2);
    float2 w8 = cmul(w4, w4);
    float2 wA = make_float2(1.f, 0.f), wB = w4, wC = w8, wD = cmul(w8, w4);
    int base = t*16 + c;
    #pragma unroll
    for (int b = 0; b < 4; ++b) {
        S[(b)     * 256 + base] = (b == 0) ? x[0] : cmul(x[b],      wA);
        S[(b + 4) * 256 + base] = cmul(x[b + 4],  wB);
        S[(b + 8) * 256 + base] = cmul(x[b + 8],  wC);
        S[(b + 12)* 256 + base] = cmul(x[b + 12], wD);
        if (b == 0) wA = w1; else wA = cmul(wA, w1);
        wB = cmul(wB, w1);
        wC = cmul(wC, w1);
        wD = cmul(wD, w1);
    }
}

// ================= 1024-pt kernels =================

__global__ __launch_bounds__(128) void k_rows_fwd_planar(const float* __restrict__ re, const float* __restrict__ im) {
    __shared__ float2 S[4 * 1056];
    int tid = threadIdx.x;
    int r = tid >> 5, t = tid & 31;
    int row = blockIdx.x * 4 + r;
    const float* rp = re + (size_t)row * NN;
    const float* ip = im + (size_t)row * NN;
    float2 x[32];
    #pragma unroll
    for (int m = 0; m < 32; ++m) x[m] = make_float2(rp[m*32 + t], ip[m*32 + t]);
    dft32<-1>(x);
    float ss, cc; sincospif(-(float)t / 512.0f, &ss, &cc);
    tw_store32(S + r * 1056, 33, t, x, make_float2(cc, ss));
    __syncthreads();
    float2 y[32];
    float2* Sr = S + r * 1056;
    #pragma unroll
    for (int n2 = 0; n2 < 32; ++n2) y[n2] = Sr[t*33 + n2];
    dft32<-1>(y);
    float2* o = g_X + (size_t)row * NN;
    #pragma unroll
    for (int k2 = 0; k2 < 32; ++k2) o[t + 32*k2] = y[k2];
}

// rows_inv: reads ACC, re-zeroes it, writes D into g_D (fp32)
__global__ __launch_bounds__(128) void k_rows_inv_acc() {
    __shared__ float2 S[4 * 1056];
    int tid = threadIdx.x;
    int r = tid >> 5, t = tid & 31;
    int row = blockIdx.x * 4 + r;
    float2* src = ((float2*)g_ACC) + (size_t)row * NN;
    float2 x[32];
    #pragma unroll
    for (int m = 0; m < 32; ++m) x[m] = src[m*32 + t];
    #pragma unroll
    for (int m = 0; m < 32; ++m) src[m*32 + t] = make_float2(0.f, 0.f);
    dft32<+1>(x);
    float ss, cc; sincospif((float)t / 512.0f, &ss, &cc);
    tw_store32(S + r * 1056, 33, t, x, make_float2(cc, ss));
    __syncthreads();
    float2 y[32];
    float2* Sr = S + r * 1056;
    #pragma unroll
    for (int n2 = 0; n2 < 32; ++n2) y[n2] = Sr[t*33 + n2];
    dft32<+1>(y);
    float2* o = g_D + (size_t)row * NN;
    #pragma unroll
    for (int k2 = 0; k2 < 32; ++k2) o[t + 32*k2] = y[k2];
}

#define COLS_SMEM_BYTES (8 * 1058 * (int)sizeof(float2))

__global__ __launch_bounds__(256) void k_cols_fwd_X() {
    extern __shared__ float2 S[];
    int tid = threadIdx.x;
    int c = tid & 7, t = tid >> 3;
    int b  = blockIdx.x >> 7;
    int c0 = (blockIdx.x & 127) * 8;
    float2* img = g_X + (size_t)b * NN * NN;
    float2 x[32];
    #pragma unroll
    for (int m = 0; m < 32; ++m) x[m] = img[(size_t)(m*32 + t) * NN + c0 + c];
    dft32<-1>(x);
    float ss, cc; sincospif(-(float)t / 512.0f, &ss, &cc);
    tw_store32(S + c * 1058, 33, t, x, make_float2(cc, ss));
    __syncthreads();
    float2 y[32];
    float2* Sc = S + c * 1058;
    #pragma unroll
    for (int n2 = 0; n2 < 32; ++n2) y[n2] = Sc[t*33 + n2];
    dft32<-1>(y);
    #pragma unroll
    for (int k2 = 0; k2 < 32; ++k2) img[(size_t)(t + 32*k2) * NN + c0 + c] = y[k2];
}

__global__ __launch_bounds__(256) void k_cols_inv_final(const float* __restrict__ img_a, const float* __restrict__ xre,
                                 const float* __restrict__ xim,  const float* __restrict__ lamb,
                                 const float* __restrict__ eta1, float* __restrict__ out,
                                 long long out_size) {
    extern __shared__ float2 S[];
    int tid = threadIdx.x;
    int c = tid & 7, t = tid >> 3;
    int b  = blockIdx.x >> 7;
    int c0 = (blockIdx.x & 127) * 8;
    const float2* img = g_D + (size_t)b * NN * NN;
    float2 x[32];
    #pragma unroll
    for (int m = 0; m < 32; ++m) x[m] = img[(size_t)(m*32 + t) * NN + c0 + c];
    dft32<+1>(x);
    float ss, cc; sincospif((float)t / 512.0f, &ss, &cc);
    tw_store32(S + c * 1058, 33, t, x, make_float2(cc, ss));
    __syncthreads();
    float2 y[32];
    float2* Sc = S + c * 1058;
    #pragma unroll
    for (int n2 = 0; n2 < 32; ++n2) y[n2] = Sc[t*33 + n2];
    dft32<+1>(y);
    float e1  = eta1[0];
    float lm  = lamb[0];
    float bco = 100.0f * e1 * lm;
    float aco = 10.0f  * e1;
    float coef = aco / ((float)LL * 1048576.0f);
    float one_m_b = 1.0f - bco;
    #pragma unroll
    for (int k2 = 0; k2 < 32; ++k2) {
        int rrow = t + 32*k2;
        long long idx = ((long long)b * NN + rrow) * NN + c0 + c;
        float2 d = y[k2];
        float xr = xre[idx], xi = xim[idx];
        float m  = sqrtf(fmaf(xr, xr, xi * xi)) + 1e-6f;
        float fa = bco * img_a[idx] / m;
        float rcx = one_m_b * xr - coef * d.x + fa * xr;
        float rcy = one_m_b * xi - coef * d.y + fa * xi;
        if (idx < out_size) out[idx] = sqrtf(fmaf(rcx, rcx, rcy * rcy));
        long long ore = (long long)IMG_PIX + idx;
        long long oim = (long long)(2 * IMG_PIX) + idx;
        if (ore < out_size) out[ore] = rcx;
        if (oim < out_size) out[oim] = rcy;
    }
}

// ================= patch kernels (half2 intermediates) =================

__global__ __launch_bounds__(256) void k_p1(const int* __restrict__ masks, const float* __restrict__ ctf) {
    __shared__ float2 S[16 * 272];
    int tid = threadIdx.x;
    int r = tid >> 4, t = tid & 15;
    int rg = blockIdx.x & 15;
    int pk = blockIdx.x >> 4;
    int b  = pk >> 6, k = pk & 63;
    int mr = masks[2*k] - 1, mc = masks[2*k+1] - 1;
    int i  = (rg << 4) + r;
    int gr = (mr + i + 512) & 1023;
    const float2* Xrow = g_X + ((size_t)b * NN + gr) * NN;
    const float*  cfr  = ctf + i * NP;
    float2 x[16];
    const float sc = 1.0f / 256.0f;               // range-fold for half storage
    #pragma unroll
    for (int m = 0; m < 16; ++m) {
        int j  = m*16 + t;
        int gc = (mc + j + 512) & 1023;
        float2 v = Xrow[gc];
        float cf = cfr[j] * sc;
        x[m] = make_float2(v.x * cf, v.y * cf);
    }
    dft16<+1>(x);
    float ss, cc; sincospif(2.0f * (float)t / 256.0f, &ss, &cc);
    tw_store16(S + r * 272, 17, t, x, make_float2(cc, ss));
    __syncthreads();
    float2 y[16];
    float2* Sr = S + r * 272;
    #pragma unroll
    for (int n2 = 0; n2 < 16; ++n2) y[n2] = Sr[t*17 + n2];
    dft16<+1>(y);
    __half2* o = g_S1h + ((size_t)pk * NP + i) * NP;
    #pragma unroll
    for (int k2 = 0; k2 < 16; ++k2) o[t + 16*k2] = f2h(y[k2]);
}

__global__ __launch_bounds__(256) void k_p2(const float* __restrict__ Y) {
    __shared__ float2 S[16 * 256];
    __shared__ float Ysm[256 * 16];
    int tid = threadIdx.x;
    int t = tid >> 4, c = tid & 15;
    int pk = blockIdx.x >> 4;
    int c0 = (blockIdx.x & 15) << 4;
    // prefetch Y tile (coalesced, overlaps the first FFT phase; first sync covers it)
    const float* Yp = Y + (size_t)pk * NP * NP;
    #pragma unroll
    for (int q = 0; q < 16; ++q) {
        int idx = tid + q * 256;                   // 4096 values
        int row = idx >> 4, col = idx & 15;
        Ysm[idx] = Yp[row * NP + c0 + col];
    }
    __half2* P = g_S1h + (size_t)pk * NP * NP;
    float2 x[16];
    #pragma unroll
    for (int m = 0; m < 16; ++m) x[m] = h2f(P[(m*16 + t) * NP + c0 + c]);
    dft16<+1>(x);
    float ss, cc; sincospif(2.0f * (float)t / 256.0f, &ss, &cc);
    float2 w1inv = make_float2(cc, ss);
    tw_store16_p2(S, t, c, x, w1inv);
    __syncthreads();
    float2 y[16];
    #pragma unroll
    for (int n2 = 0; n2 < 16; ++n2) y[n2] = S[t*256 + n2*16 + c];
    dft16<+1>(y);
    const float inv = 1.0f / 256.0f;               // remaining ifft2 norm (1/256 folded at p1)
    #pragma unroll
    for (int k2 = 0; k2 < 16; ++k2) {
        float2 wv = make_float2(y[k2].x * inv, y[k2].y * inv);
        float mag2 = fmaf(wv.x, wv.x, wv.y * wv.y);
        float yv   = Ysm[(t + 16*k2) * 16 + c];
        if (mag2 > 0.0f) {
            float f = 1.0f - sqrtf(__fdividef(yv, mag2));
            y[k2] = make_float2(wv.x * f, wv.y * f);
        } else {
            y[k2] = make_float2(-sqrtf(yv), 0.0f);
        }
    }
    dft16<-1>(y);
    __syncthreads();
    tw_store16_p2(S, t, c, y, conjf2(w1inv));
    __syncthreads();
    float2 z[16];
    #pragma unroll
    for (int n2 = 0; n2 < 16; ++n2) z[n2] = S[t*256 + n2*16 + c];
    dft16<-1>(z);
    #pragma unroll
    for (int k2 = 0; k2 < 16; ++k2) P[(t + 16*k2) * NP + c0 + c] = f2h(z[k2]);
}

__global__ __launch_bounds__(256) void k_p3(const int* __restrict__ masks, const float* __restrict__ ctf) {
    __shared__ float2 S[16 * 272];
    int tid = threadIdx.x;
    int r = tid >> 4, t = tid & 15;
    int rg = blockIdx.x & 15;
    int pk = blockIdx.x >> 4;
    int b  = pk >> 6, k = pk & 63;
    int mr = masks[2*k] - 1, mc = masks[2*k+1] - 1;
    int i  = (rg << 4) + r;
    const __half2* src = g_S1h + ((size_t)pk * NP + i) * NP;
    float2 x[16];
    #pragma unroll
    for (int m = 0; m < 16; ++m) x[m] = h2f(src[m*16 + t]);
    dft16<-1>(x);
    float ss, cc; sincospif(-2.0f * (float)t / 256.0f, &ss, &cc);
    tw_store16(S + r * 272, 17, t, x, make_float2(cc, ss));
    __syncthreads();
    float2 y[16];
    float2* Sr = S + r * 272;
    #pragma unroll
    for (int n2 = 0; n2 < 16; ++n2) y[n2] = Sr[t*17 + n2];
    dft16<-1>(y);
    int gr = (mr + i + 512) & 1023;
    float* accrow = g_ACC + ((size_t)b * NN + gr) * NN * 2;
    const float* cfr = ctf + i * NP;
    #pragma unroll
    for (int k2 = 0; k2 < 16; ++k2) {
        int j  = t + 16*k2;
        float cf = cfr[j];
        int gc = (mc + j + 512) & 1023;
        red_add_v2(accrow + gc*2, y[k2].x * cf, y[k2].y * cf);
    }
}

// ---------------- launch ----------------
extern "C" void kernel_launch(void* const* d_in, const int* in_sizes, int n_in,
                              void* d_out, int out_size) {
    const float* Img_a = (const float*)d_in[0];
    const float* Xre   = (const float*)d_in[1];
    const float* Xim   = (const float*)d_in[2];
    const float* Y     = (const float*)d_in[3];
    const int*   Masks = (const int*)  d_in[4];
    const float* CTF   = (const float*)d_in[5];
    const float* lamb  = (const float*)d_in[6];
    const float* eta1  = (const float*)d_in[7];
    float* out = (float*)d_out;

    cudaFuncSetAttribute((const void*)k_cols_fwd_X,
                         cudaFuncAttributeMaxDynamicSharedMemorySize, COLS_SMEM_BYTES);
    cudaFuncSetAttribute((const void*)k_cols_inv_final,
                         cudaFuncAttributeMaxDynamicSharedMemorySize, COLS_SMEM_BYTES);

    k_rows_fwd_planar<<<BATCH * NN / 4, 128>>>(Xre, Xim);
    k_cols_fwd_X<<<BATCH * 128, 256, COLS_SMEM_BYTES>>>();
    k_p1<<<BATCH * LL * 16, 256>>>(Masks, CTF);
    k_p2<<<BATCH * LL * 16, 256>>>(Y);
    k_p3<<<BATCH * LL * 16, 256>>>(Masks, CTF);
    k_rows_inv_acc<<<BATCH * NN / 4, 128>>>();
    k_cols_inv_final<<<BATCH * 128, 256, COLS_SMEM_BYTES>>>(
        Img_a, Xre, Xim, lamb, eta1, out, (long long)out_size);
}

// round 12
// speedup vs baseline: 1.4808x; 1.0480x over previous
#include <cuda_runtime.h>
#include <cuda_fp16.h>
#include <cstdint>

#define BATCH 4
#define NN 1024
#define LL 64
#define NP 256
#define IMG_PIX (BATCH * NN * NN)

// ---------------- scratch ----------------
__device__ float2  g_X[BATCH * NN * NN];              // fp32 spectrum
__device__ __half2 g_S1h[BATCH * LL * NP * NP];       // half2 patch scratch
__device__ float   g_ACC[BATCH * NN * NN * 2];        // fp32 accumulator
__device__ float2  g_D[BATCH * NN * NN];              // fp32 D intermediate

// ---------------- packed complex (Blackwell f32x2) ----------------
typedef unsigned long long cplx;

__device__ __forceinline__ cplx mkc(float x, float y){ cplx r; asm("mov.b64 %0,{%1,%2};":"=l"(r):"f"(x),"f"(y)); return r; }
__device__ __forceinline__ void gxy(cplx v, float& x, float& y){ asm("mov.b64 {%0,%1},%2;":"=f"(x),"=f"(y):"l"(v)); }
__device__ __forceinline__ cplx cadd(cplx a, cplx b){ cplx r; asm("add.rn.f32x2 %0,%1,%2;":"=l"(r):"l"(a),"l"(b)); return r; }
__device__ __forceinline__ cplx csub(cplx a, cplx b){
    const cplx NEG1 = 0xBF800000BF800000ULL;          // packed {-1.f,-1.f}
    cplx r; asm("fma.rn.f32x2 %0,%1,%2,%3;":"=l"(r):"l"(b),"l"(NEG1),"l"(a)); return r;   // a - b exactly
}
// packed * scalar-pair twiddle (twiddles stay scalar -> FFMA immediate forms)
__device__ __forceinline__ cplx cmulw(cplx a, float2 w){
    float ax, ay; gxy(a, ax, ay);
    return mkc(fmaf(ax, w.x, -ay*w.y), fmaf(ax, w.y, ay*w.x));
}
// scalar complex mul for twiddle chains
__device__ __forceinline__ float2 cmulf(float2 a, float2 b){
    return make_float2(fmaf(a.x,b.x,-a.y*b.y), fmaf(a.x,b.y,a.y*b.x));
}
__device__ __forceinline__ float2 conjf2(float2 a){ return make_float2(a.x, -a.y); }
__device__ __forceinline__ cplx h2c(__half2 h){ float2 f = __half22float2(h); return mkc(f.x, f.y); }

// packed float2 global reduction (sm_90+)
__device__ __forceinline__ void red_add_v2(float* addr, float vx, float vy) {
    asm volatile("red.global.add.v2.f32 [%0], {%1, %2};"
                 :: "l"(addr), "f"(vx), "f"(vy) : "memory");
}

// ---------------- register DFT16 (packed butterflies) ----------------
template<int SGN>
__device__ __forceinline__ void dft16(cplx* r) {
    const float C1 = 0.923879532511287f, S1 = 0.382683432365090f, C2 = 0.707106781186548f;
    const float2 W[8] = {
        {1.f, 0.f}, {C1, SGN*S1}, {C2, SGN*C2}, {S1, SGN*C1},
        {0.f, SGN*1.f}, {-S1, SGN*C1}, {-C2, SGN*C2}, {-C1, SGN*S1}
    };
    cplx t[16];
    #pragma unroll
    for (int j = 0; j < 8; ++j) {
        cplx a = r[j], b = r[j+8];
        t[2*j]   = cadd(a, b);
        t[2*j+1] = cmulw(csub(a, b), W[j]);
    }
    #pragma unroll
    for (int j = 0; j < 8; ++j) {
        int off = j & ~1;
        cplx a = t[j], b = t[j+8];
        r[j+off]   = cadd(a, b);
        r[j+off+2] = cmulw(csub(a, b), W[off]);
    }
    #pragma unroll
    for (int j = 0; j < 8; ++j) {
        int off = j & ~3;
        cplx a = r[j], b = r[j+8];
        t[j+off]   = cadd(a, b);
        t[j+off+4] = cmulw(csub(a, b), W[off]);
    }
    #pragma unroll
    for (int j = 0; j < 8; ++j) {
        cplx a = t[j], b = t[j+8];
        r[j]   = cadd(a, b);
        r[j+8] = csub(a, b);
    }
}

// ---------------- register DFT32 (packed butterflies) ----------------
template<int SGN>
__device__ __forceinline__ void dft32(cplx* r) {
    const float A1 = 0.980785280403230f, B1 = 0.195090322016128f;
    const float A2 = 0.923879532511287f, B2 = 0.382683432365090f;
    const float A3 = 0.831469612302545f, B3 = 0.555570233019602f;
    const float A4 = 0.707106781186548f;
    const float2 W[16] = {
        {1.f, 0.f},      {A1, SGN*B1},   {A2, SGN*B2},   {A3, SGN*B3},
        {A4, SGN*A4},    {B3, SGN*A3},   {B2, SGN*A2},   {B1, SGN*A1},
        {0.f, SGN*1.f},  {-B1, SGN*A1},  {-B2, SGN*A2},  {-B3, SGN*A3},
        {-A4, SGN*A4},   {-A3, SGN*B3},  {-A2, SGN*B2},  {-A1, SGN*B1}
    };
    cplx t[32];
    #pragma unroll
    for (int j = 0; j < 16; ++j) {
        cplx a = r[j], b = r[j+16];
        t[2*j]   = cadd(a, b);
        t[2*j+1] = cmulw(csub(a, b), W[j]);
    }
    #pragma unroll
    for (int j = 0; j < 16; ++j) {
        int off = j & ~1;
        cplx a = t[j], b = t[j+16];
        r[j+off]   = cadd(a, b);
        r[j+off+2] = cmulw(csub(a, b), W[off]);
    }
    #pragma unroll
    for (int j = 0; j < 16; ++j) {
        int off = j & ~3;
        cplx a = r[j], b = r[j+16];
        t[j+off]   = cadd(a, b);
        t[j+off+4] = cmulw(csub(a, b), W[off]);
    }
    #pragma unroll
    for (int j = 0; j < 16; ++j) {
        int off = j & ~7;
        cplx a = t[j], b = t[j+16];
        r[j+off]   = cadd(a, b);
        r[j+off+8] = cmulw(csub(a, b), W[off]);
    }
    #pragma unroll
    for (int j = 0; j < 16; ++j) {
        cplx a = r[j], b = r[j+16];
        t[j]    = cadd(a, b);
        t[j+16] = csub(a, b);
    }
    #pragma unroll
    for (int j = 0; j < 32; ++j) r[j] = t[j];
}

// chain-split twiddle stores (scalar chains, packed data)
__device__ __forceinline__ void tw_store16(cplx* S, int ST, int t, const cplx* x, float2 w1) {
    float2 w2 = cmulf(w1, w1);
    float2 w4 = cmulf(w2, w2);
    float2 w8 = cmulf(w4, w4);
    float2 wA = make_float2(1.f, 0.f), wB = w4, wC = w8, wD = cmulf(w8, w4);
    #pragma unroll
    for (int b = 0; b < 4; ++b) {
        S[(b)     * ST + t] = (b == 0) ? x[0] : cmulw(x[b],      wA);
        S[(b + 4) * ST + t] = cmulw(x[b + 4],  wB);
        S[(b + 8) * ST + t] = cmulw(x[b + 8],  wC);
        S[(b + 12)* ST + t] = cmulw(x[b + 12], wD);
        if (b == 0) wA = w1; else wA = cmulf(wA, w1);
        wB = cmulf(wB, w1);
        wC = cmulf(wC, w1);
        wD = cmulf(wD, w1);
    }
}

__device__ __forceinline__ void tw_store32(cplx* S, int ST, int t, const cplx* x, float2 w1) {
    float2 w2  = cmulf(w1, w1);
    float2 w4  = cmulf(w2, w2);
    float2 w8  = cmulf(w4, w4);
    float2 w16 = cmulf(w8, w8);
    float2 wA = make_float2(1.f, 0.f), wB = w8, wC = w16, wD = cmulf(w16, w8);
    #pragma unroll
    for (int b = 0; b < 8; ++b) {
        S[(b)      * ST + t] = (b == 0) ? x[0] : cmulw(x[b],       wA);
        S[(b + 8)  * ST + t] = cmulw(x[b + 8],   wB);
        S[(b + 16) * ST + t] = cmulw(x[b + 16],  wC);
        S[(b + 24) * ST + t] = cmulw(x[b + 24],  wD);
        if (b == 0) wA = w1; else wA = cmulf(wA, w1);
        wB = cmulf(wB, w1);
        wC = cmulf(wC, w1);
        wD = cmulf(wD, w1);
    }
}

__device__ __forceinline__ void tw_store16_p2(cplx* S, int t, int c, const cplx* x, float2 w1) {
    float2 w2 = cmulf(w1, w1);
    float2 w4 = cmulf(w2, w2);
    float2 w8 = cmulf(w4, w4);
    float2 wA = make_float2(1.f, 0.f), wB = w4, wC = w8, wD = cmulf(w8, w4);
    int base = t*16 + c;
    #pragma unroll
    for (int b = 0; b < 4; ++b) {
        S[(b)     * 256 + base] = (b == 0) ? x[0] : cmulw(x[b],      wA);
        S[(b + 4) * 256 + base] = cmulw(x[b + 4],  wB);
        S[(b + 8) * 256 + base] = cmulw(x[b + 8],  wC);
        S[(b + 12)* 256 + base] = cmulw(x[b + 12], wD);
        if (b == 0) wA = w1; else wA = cmulf(wA, w1);
        wB = cmulf(wB, w1);
        wC = cmulf(wC, w1);
        wD = cmulf(wD, w1);
    }
}

// ================= 1024-pt kernels =================

__global__ __launch_bounds__(128) void k_rows_fwd_planar(const float* __restrict__ re, const float* __restrict__ im) {
    __shared__ cplx S[4 * 1056];
    int tid = threadIdx.x;
    int r = tid >> 5, t = tid & 31;
    int row = blockIdx.x * 4 + r;
    const float* rp = re + (size_t)row * NN;
    const float* ip = im + (size_t)row * NN;
    cplx x[32];
    #pragma unroll
    for (int m = 0; m < 32; ++m) x[m] = mkc(rp[m*32 + t], ip[m*32 + t]);
    dft32<-1>(x);
    float ss, cc; sincospif(-(float)t / 512.0f, &ss, &cc);
    tw_store32(S + r * 1056, 33, t, x, make_float2(cc, ss));
    __syncthreads();
    cplx y[32];
    cplx* Sr = S + r * 1056;
    #pragma unroll
    for (int n2 = 0; n2 < 32; ++n2) y[n2] = Sr[t*33 + n2];
    dft32<-1>(y);
    cplx* o = ((cplx*)g_X) + (size_t)row * NN;
    #pragma unroll
    for (int k2 = 0; k2 < 32; ++k2) o[t + 32*k2] = y[k2];
}

// rows_inv: reads ACC, re-zeroes it, writes D into g_D (fp32)
__global__ __launch_bounds__(128) void k_rows_inv_acc() {
    __shared__ cplx S[4 * 1056];
    int tid = threadIdx.x;
    int r = tid >> 5, t = tid & 31;
    int row = blockIdx.x * 4 + r;
    cplx* src = ((cplx*)g_ACC) + (size_t)row * NN;
    cplx x[32];
    #pragma unroll
    for (int m = 0; m < 32; ++m) x[m] = src[m*32 + t];
    #pragma unroll
    for (int m = 0; m < 32; ++m) src[m*32 + t] = 0ULL;
    dft32<+1>(x);
    float ss, cc; sincospif((float)t / 512.0f, &ss, &cc);
    tw_store32(S + r * 1056, 33, t, x, make_float2(cc, ss));
    __syncthreads();
    cplx y[32];
    cplx* Sr = S + r * 1056;
    #pragma unroll
    for (int n2 = 0; n2 < 32; ++n2) y[n2] = Sr[t*33 + n2];
    dft32<+1>(y);
    cplx* o = ((cplx*)g_D) + (size_t)row * NN;
    #pragma unroll
    for (int k2 = 0; k2 < 32; ++k2) o[t + 32*k2] = y[k2];
}

#define COLS_SMEM_BYTES (8 * 1058 * (int)sizeof(cplx))

__global__ __launch_bounds__(256) void k_cols_fwd_X() {
    extern __shared__ cplx S[];
    int tid = threadIdx.x;
    int c = tid & 7, t = tid >> 3;
    int b  = blockIdx.x >> 7;
    int c0 = (blockIdx.x & 127) * 8;
    cplx* img = ((cplx*)g_X) + (size_t)b * NN * NN;
    cplx x[32];
    #pragma unroll
    for (int m = 0; m < 32; ++m) x[m] = img[(size_t)(m*32 + t) * NN + c0 + c];
    dft32<-1>(x);
    float ss, cc; sincospif(-(float)t / 512.0f, &ss, &cc);
    tw_store32(S + c * 1058, 33, t, x, make_float2(cc, ss));
    __syncthreads();
    cplx y[32];
    cplx* Sc = S + c * 1058;
    #pragma unroll
    for (int n2 = 0; n2 < 32; ++n2) y[n2] = Sc[t*33 + n2];
    dft32<-1>(y);
    #pragma unroll
    for (int k2 = 0; k2 < 32; ++k2) img[(size_t)(t + 32*k2) * NN + c0 + c] = y[k2];
}

__global__ __launch_bounds__(256) void k_cols_inv_final(const float* __restrict__ img_a, const float* __restrict__ xre,
                                 const float* __restrict__ xim,  const float* __restrict__ lamb,
                                 const float* __restrict__ eta1, float* __restrict__ out,
                                 long long out_size) {
    extern __shared__ cplx S[];
    int tid = threadIdx.x;
    int c = tid & 7, t = tid >> 3;
    int b  = blockIdx.x >> 7;
    int c0 = (blockIdx.x & 127) * 8;
    const cplx* img = ((const cplx*)g_D) + (size_t)b * NN * NN;
    cplx x[32];
    #pragma unroll
    for (int m = 0; m < 32; ++m) x[m] = img[(size_t)(m*32 + t) * NN + c0 + c];
    dft32<+1>(x);
    float ss, cc; sincospif((float)t / 512.0f, &ss, &cc);
    tw_store32(S + c * 1058, 33, t, x, make_float2(cc, ss));
    __syncthreads();
    cplx y[32];
    cplx* Sc = S + c * 1058;
    #pragma unroll
    for (int n2 = 0; n2 < 32; ++n2) y[n2] = Sc[t*33 + n2];
    dft32<+1>(y);
    float e1  = eta1[0];
    float lm  = lamb[0];
    float bco = 100.0f * e1 * lm;
    float aco = 10.0f  * e1;
    float coef = aco / ((float)LL * 1048576.0f);
    float one_m_b = 1.0f - bco;
    #pragma unroll
    for (int k2 = 0; k2 < 32; ++k2) {
        int rrow = t + 32*k2;
        long long idx = ((long long)b * NN + rrow) * NN + c0 + c;
        float dx, dy; gxy(y[k2], dx, dy);
        float xr = xre[idx], xi = xim[idx];
        float m  = sqrtf(fmaf(xr, xr, xi * xi)) + 1e-6f;
        float fa = bco * img_a[idx] / m;
        float rcx = one_m_b * xr - coef * dx + fa * xr;
        float rcy = one_m_b * xi - coef * dy + fa * xi;
        if (idx < out_size) out[idx] = sqrtf(fmaf(rcx, rcx, rcy * rcy));
        long long ore = (long long)IMG_PIX + idx;
        long long oim = (long long)(2 * IMG_PIX) + idx;
        if (ore < out_size) out[ore] = rcx;
        if (oim < out_size) out[oim] = rcy;
    }
}

// ================= patch kernels (half2 intermediates) =================

__global__ __launch_bounds__(256) void k_p1(const int* __restrict__ masks, const float* __restrict__ ctf) {
    __shared__ cplx S[16 * 272];
    int tid = threadIdx.x;
    int r = tid >> 4, t = tid & 15;
    int rg = blockIdx.x & 15;
    int pk = blockIdx.x >> 4;
    int b  = pk >> 6, k = pk & 63;
    int mr = masks[2*k] - 1, mc = masks[2*k+1] - 1;
    int i  = (rg << 4) + r;
    int gr = (mr + i + 512) & 1023;
    const float2* Xrow = g_X + ((size_t)b * NN + gr) * NN;
    const float*  cfr  = ctf + i * NP;
    cplx x[16];
    const float sc = 1.0f / 256.0f;               // range-fold for half storage
    #pragma unroll
    for (int m = 0; m < 16; ++m) {
        int j  = m*16 + t;
        int gc = (mc + j + 512) & 1023;
        float2 v = Xrow[gc];
        float cf = cfr[j] * sc;
        x[m] = mkc(v.x * cf, v.y * cf);
    }
    dft16<+1>(x);
    float ss, cc; sincospif(2.0f * (float)t / 256.0f, &ss, &cc);
    tw_store16(S + r * 272, 17, t, x, make_float2(cc, ss));
    __syncthreads();
    cplx y[16];
    cplx* Sr = S + r * 272;
    #pragma unroll
    for (int n2 = 0; n2 < 16; ++n2) y[n2] = Sr[t*17 + n2];
    dft16<+1>(y);
    __half2* o = g_S1h + ((size_t)pk * NP + i) * NP;
    #pragma unroll
    for (int k2 = 0; k2 < 16; ++k2) {
        float a, bb; gxy(y[k2], a, bb);
        o[t + 16*k2] = __floats2half2_rn(a, bb);
    }
}

__global__ __launch_bounds__(256) void k_p2(const float* __restrict__ Y) {
    __shared__ cplx S[16 * 256];
    __shared__ float Ysm[256 * 16];
    int tid = threadIdx.x;
    int t = tid >> 4, c = tid & 15;
    int pk = blockIdx.x >> 4;
    int c0 = (blockIdx.x & 15) << 4;
    // prefetch Y tile (coalesced; first sync covers it)
    const float* Yp = Y + (size_t)pk * NP * NP;
    #pragma unroll
    for (int q = 0; q < 16; ++q) {
        int idx = tid + q * 256;
        int row = idx >> 4, col = idx & 15;
        Ysm[idx] = Yp[row * NP + c0 + col];
    }
    __half2* P = g_S1h + (size_t)pk * NP * NP;
    cplx x[16];
    #pragma unroll
    for (int m = 0; m < 16; ++m) x[m] = h2c(P[(m*16 + t) * NP + c0 + c]);
    dft16<+1>(x);
    float ss, cc; sincospif(2.0f * (float)t / 256.0f, &ss, &cc);
    float2 w1inv = make_float2(cc, ss);
    tw_store16_p2(S, t, c, x, w1inv);
    __syncthreads();
    cplx y[16];
    #pragma unroll
    for (int n2 = 0; n2 < 16; ++n2) y[n2] = S[t*256 + n2*16 + c];
    dft16<+1>(y);
    const float inv = 1.0f / 256.0f;
    #pragma unroll
    for (int k2 = 0; k2 < 16; ++k2) {
        float wx, wy; gxy(y[k2], wx, wy);
        wx *= inv; wy *= inv;
        float mag2 = fmaf(wx, wx, wy * wy);
        float yv   = Ysm[(t + 16*k2) * 16 + c];
        if (mag2 > 0.0f) {
            float f = 1.0f - sqrtf(__fdividef(yv, mag2));
            y[k2] = mkc(wx * f, wy * f);
        } else {
            y[k2] = mkc(-sqrtf(yv), 0.0f);
        }
    }
    dft16<-1>(y);
    __syncthreads();
    tw_store16_p2(S, t, c, y, conjf2(w1inv));
    __syncthreads();
    cplx z[16];
    #pragma unroll
    for (int n2 = 0; n2 < 16; ++n2) z[n2] = S[t*256 + n2*16 + c];
    dft16<-1>(z);
    #pragma unroll
    for (int k2 = 0; k2 < 16; ++k2) {
        float a, bb; gxy(z[k2], a, bb);
        P[(t + 16*k2) * NP + c0 + c] = __floats2half2_rn(a, bb);
    }
}

__global__ __launch_bounds__(256) void k_p3(const int* __restrict__ masks, const float* __restrict__ ctf) {
    __shared__ cplx S[16 * 272];
    int tid = threadIdx.x;
    int r = tid >> 4, t = tid & 15;
    int rg = blockIdx.x & 15;
    int pk = blockIdx.x >> 4;
    int b  = pk >> 6, k = pk & 63;
    int mr = masks[2*k] - 1, mc = masks[2*k+1] - 1;
    int i  = (rg << 4) + r;
    const __half2* src = g_S1h + ((size_t)pk * NP + i) * NP;
    cplx x[16];
    #pragma unroll
    for (int m = 0; m < 16; ++m) x[m] = h2c(src[m*16 + t]);
    dft16<-1>(x);
    float ss, cc; sincospif(-2.0f * (float)t / 256.0f, &ss, &cc);
    tw_store16(S + r * 272, 17, t, x, make_float2(cc, ss));
    __syncthreads();
    cplx y[16];
    cplx* Sr = S + r * 272;
    #pragma unroll
    for (int n2 = 0; n2 < 16; ++n2) y[n2] = Sr[t*17 + n2];
    dft16<-1>(y);
    int gr = (mr + i + 512) & 1023;
    float* accrow = g_ACC + ((size_t)b * NN + gr) * NN * 2;
    const float* cfr = ctf + i * NP;
    #pragma unroll
    for (int k2 = 0; k2 < 16; ++k2) {
        int j  = t + 16*k2;
        float cf = cfr[j];
        float a, bb; gxy(y[k2], a, bb);
        int gc = (mc + j + 512) & 1023;
        red_add_v2(accrow + gc*2, a * cf, bb * cf);
    }
}

// ---------------- launch ----------------
extern "C" void kernel_launch(void* const* d_in, const int* in_sizes, int n_in,
                              void* d_out, int out_size) {
    const float* Img_a = (const float*)d_in[0];
    const float* Xre   = (const float*)d_in[1];
    const float* Xim   = (const float*)d_in[2];
    const float* Y     = (const float*)d_in[3];
    const int*   Masks = (const int*)  d_in[4];
    const float* CTF   = (const float*)d_in[5];
    const float* lamb  = (const float*)d_in[6];
    const float* eta1  = (const float*)d_in[7];
    float* out = (float*)d_out;

    cudaFuncSetAttribute((const void*)k_cols_fwd_X,
                         cudaFuncAttributeMaxDynamicSharedMemorySize, COLS_SMEM_BYTES);
    cudaFuncSetAttribute((const void*)k_cols_inv_final,
                         cudaFuncAttributeMaxDynamicSharedMemorySize, COLS_SMEM_BYTES);

    k_rows_fwd_planar<<<BATCH * NN / 4, 128>>>(Xre, Xim);
    k_cols_fwd_X<<<BATCH * 128, 256, COLS_SMEM_BYTES>>>();
    k_p1<<<BATCH * LL * 16, 256>>>(Masks, CTF);
    k_p2<<<BATCH * LL * 16, 256>>>(Y);
    k_p3<<<BATCH * LL * 16, 256>>>(Masks, CTF);
    k_rows_inv_acc<<<BATCH * NN / 4, 128>>>();
    k_cols_inv_final<<<BATCH * 128, 256, COLS_SMEM_BYTES>>>(
        Img_a, Xre, Xim, lamb, eta1, out, (long long)out_size);
}

// round 13
// speedup vs baseline: 1.5056x; 1.0167x over previous
#include <cuda_runtime.h>
#include <cuda_fp16.h>
#include <cstdint>

#define BATCH 4
#define NN 1024
#define LL 64
#define NP 256
#define IMG_PIX (BATCH * NN * NN)

// ---------------- scratch ----------------
__device__ __half2 g_Xh[BATCH * NN * NN];             // half2 spectrum (16.7MB) — feeds data term only
__device__ __half2 g_S1h[BATCH * LL * NP * NP];       // half2 patch scratch
__device__ float   g_ACC[BATCH * NN * NN * 2];        // fp32 accumulator
__device__ __half2 g_Dh[BATCH * NN * NN];             // half2 D intermediate (scaled 1/1024)

// ---------------- packed complex (Blackwell f32x2) ----------------
typedef unsigned long long cplx;

__device__ __forceinline__ cplx mkc(float x, float y){ cplx r; asm("mov.b64 %0,{%1,%2};":"=l"(r):"f"(x),"f"(y)); return r; }
__device__ __forceinline__ void gxy(cplx v, float& x, float& y){ asm("mov.b64 {%0,%1},%2;":"=f"(x),"=f"(y):"l"(v)); }
__device__ __forceinline__ cplx cadd(cplx a, cplx b){ cplx r; asm("add.rn.f32x2 %0,%1,%2;":"=l"(r):"l"(a),"l"(b)); return r; }
__device__ __forceinline__ cplx csub(cplx a, cplx b){
    const cplx NEG1 = 0xBF800000BF800000ULL;          // packed {-1.f,-1.f}
    cplx r; asm("fma.rn.f32x2 %0,%1,%2,%3;":"=l"(r):"l"(b),"l"(NEG1),"l"(a)); return r;   // a - b exactly
}
__device__ __forceinline__ cplx cmulw(cplx a, float2 w){
    float ax, ay; gxy(a, ax, ay);
    return mkc(fmaf(ax, w.x, -ay*w.y), fmaf(ax, w.y, ay*w.x));
}
__device__ __forceinline__ float2 cmulf(float2 a, float2 b){
    return make_float2(fmaf(a.x,b.x,-a.y*b.y), fmaf(a.x,b.y,a.y*b.x));
}
__device__ __forceinline__ float2 conjf2(float2 a){ return make_float2(a.x, -a.y); }
__device__ __forceinline__ cplx h2c(__half2 h){ float2 f = __half22float2(h); return mkc(f.x, f.y); }
__device__ __forceinline__ __half2 c2h(cplx v){ float a,b; gxy(v,a,b); return __floats2half2_rn(a,b); }

// packed float2 global reduction (sm_90+)
__device__ __forceinline__ void red_add_v2(float* addr, float vx, float vy) {
    asm volatile("red.global.add.v2.f32 [%0], {%1, %2};"
                 :: "l"(addr), "f"(vx), "f"(vy) : "memory");
}

// ---------------- register DFT16 (packed butterflies) ----------------
template<int SGN>
__device__ __forceinline__ void dft16(cplx* r) {
    const float C1 = 0.923879532511287f, S1 = 0.382683432365090f, C2 = 0.707106781186548f;
    const float2 W[8] = {
        {1.f, 0.f}, {C1, SGN*S1}, {C2, SGN*C2}, {S1, SGN*C1},
        {0.f, SGN*1.f}, {-S1, SGN*C1}, {-C2, SGN*C2}, {-C1, SGN*S1}
    };
    cplx t[16];
    #pragma unroll
    for (int j = 0; j < 8; ++j) {
        cplx a = r[j], b = r[j+8];
        t[2*j]   = cadd(a, b);
        t[2*j+1] = cmulw(csub(a, b), W[j]);
    }
    #pragma unroll
    for (int j = 0; j < 8; ++j) {
        int off = j & ~1;
        cplx a = t[j], b = t[j+8];
        r[j+off]   = cadd(a, b);
        r[j+off+2] = cmulw(csub(a, b), W[off]);
    }
    #pragma unroll
    for (int j = 0; j < 8; ++j) {
        int off = j & ~3;
        cplx a = r[j], b = r[j+8];
        t[j+off]   = cadd(a, b);
        t[j+off+4] = cmulw(csub(a, b), W[off]);
    }
    #pragma unroll
    for (int j = 0; j < 8; ++j) {
        cplx a = t[j], b = t[j+8];
        r[j]   = cadd(a, b);
        r[j+8] = csub(a, b);
    }
}

// ---------------- register DFT32 (packed butterflies) ----------------
template<int SGN>
__device__ __forceinline__ void dft32(cplx* r) {
    const float A1 = 0.980785280403230f, B1 = 0.195090322016128f;
    const float A2 = 0.923879532511287f, B2 = 0.382683432365090f;
    const float A3 = 0.831469612302545f, B3 = 0.555570233019602f;
    const float A4 = 0.707106781186548f;
    const float2 W[16] = {
        {1.f, 0.f},      {A1, SGN*B1},   {A2, SGN*B2},   {A3, SGN*B3},
        {A4, SGN*A4},    {B3, SGN*A3},   {B2, SGN*A2},   {B1, SGN*A1},
        {0.f, SGN*1.f},  {-B1, SGN*A1},  {-B2, SGN*A2},  {-B3, SGN*A3},
        {-A4, SGN*A4},   {-A3, SGN*B3},  {-A2, SGN*B2},  {-A1, SGN*B1}
    };
    cplx t[32];
    #pragma unroll
    for (int j = 0; j < 16; ++j) {
        cplx a = r[j], b = r[j+16];
        t[2*j]   = cadd(a, b);
        t[2*j+1] = cmulw(csub(a, b), W[j]);
    }
    #pragma unroll
    for (int j = 0; j < 16; ++j) {
        int off = j & ~1;
        cplx a = t[j], b = t[j+16];
        r[j+off]   = cadd(a, b);
        r[j+off+2] = cmulw(csub(a, b), W[off]);
    }
    #pragma unroll
    for (int j = 0; j < 16; ++j) {
        int off = j & ~3;
        cplx a = r[j], b = r[j+16];
        t[j+off]   = cadd(a, b);
        t[j+off+4] = cmulw(csub(a, b), W[off]);
    }
    #pragma unroll
    for (int j = 0; j < 16; ++j) {
        int off = j & ~7;
        cplx a = t[j], b = t[j+16];
        r[j+off]   = cadd(a, b);
        r[j+off+8] = cmulw(csub(a, b), W[off]);
    }
    #pragma unroll
    for (int j = 0; j < 16; ++j) {
        cplx a = r[j], b = r[j+16];
        t[j]    = cadd(a, b);
        t[j+16] = csub(a, b);
    }
    #pragma unroll
    for (int j = 0; j < 32; ++j) r[j] = t[j];
}

// chain-split twiddle stores (scalar chains, packed data)
__device__ __forceinline__ void tw_store16(cplx* S, int ST, int t, const cplx* x, float2 w1) {
    float2 w2 = cmulf(w1, w1);
    float2 w4 = cmulf(w2, w2);
    float2 w8 = cmulf(w4, w4);
    float2 wA = make_float2(1.f, 0.f), wB = w4, wC = w8, wD = cmulf(w8, w4);
    #pragma unroll
    for (int b = 0; b < 4; ++b) {
        S[(b)     * ST + t] = (b == 0) ? x[0] : cmulw(x[b],      wA);
        S[(b + 4) * ST + t] = cmulw(x[b + 4],  wB);
        S[(b + 8) * ST + t] = cmulw(x[b + 8],  wC);
        S[(b + 12)* ST + t] = cmulw(x[b + 12], wD);
        if (b == 0) wA = w1; else wA = cmulf(wA, w1);
        wB = cmulf(wB, w1);
        wC = cmulf(wC, w1);
        wD = cmulf(wD, w1);
    }
}

__device__ __forceinline__ void tw_store32(cplx* S, int ST, int t, const cplx* x, float2 w1) {
    float2 w2  = cmulf(w1, w1);
    float2 w4  = cmulf(w2, w2);
    float2 w8  = cmulf(w4, w4);
    float2 w16 = cmulf(w8, w8);
    float2 wA = make_float2(1.f, 0.f), wB = w8, wC = w16, wD = cmulf(w16, w8);
    #pragma unroll
    for (int b = 0; b < 8; ++b) {
        S[(b)      * ST + t] = (b == 0) ? x[0] : cmulw(x[b],       wA);
        S[(b + 8)  * ST + t] = cmulw(x[b + 8],   wB);
        S[(b + 16) * ST + t] = cmulw(x[b + 16],  wC);
        S[(b + 24) * ST + t] = cmulw(x[b + 24],  wD);
        if (b == 0) wA = w1; else wA = cmulf(wA, w1);
        wB = cmulf(wB, w1);
        wC = cmulf(wC, w1);
        wD = cmulf(wD, w1);
    }
}

__device__ __forceinline__ void tw_store16_p2(cplx* S, int t, int c, const cplx* x, float2 w1) {
    float2 w2 = cmulf(w1, w1);
    float2 w4 = cmulf(w2, w2);
    float2 w8 = cmulf(w4, w4);
    float2 wA = make_float2(1.f, 0.f), wB = w4, wC = w8, wD = cmulf(w8, w4);
    int base = t*16 + c;
    #pragma unroll
    for (int b = 0; b < 4; ++b) {
        S[(b)     * 256 + base] = (b == 0) ? x[0] : cmulw(x[b],      wA);
        S[(b + 4) * 256 + base] = cmulw(x[b + 4],  wB);
        S[(b + 8) * 256 + base] = cmulw(x[b + 8],  wC);
        S[(b + 12)* 256 + base] = cmulw(x[b + 12], wD);
        if (b == 0) wA = w1; else wA = cmulf(wA, w1);
        wB = cmulf(wB, w1);
        wC = cmulf(wC, w1);
        wD = cmulf(wD, w1);
    }
}

// ================= 1024-pt kernels =================

__global__ __launch_bounds__(128) void k_rows_fwd_planar(const float* __restrict__ re, const float* __restrict__ im) {
    __shared__ cplx S[4 * 1056];
    int tid = threadIdx.x;
    int r = tid >> 5, t = tid & 31;
    int row = blockIdx.x * 4 + r;
    const float* rp = re + (size_t)row * NN;
    const float* ip = im + (size_t)row * NN;
    cplx x[32];
    #pragma unroll
    for (int m = 0; m < 32; ++m) x[m] = mkc(rp[m*32 + t], ip[m*32 + t]);
    dft32<-1>(x);
    float ss, cc; sincospif(-(float)t / 512.0f, &ss, &cc);
    tw_store32(S + r * 1056, 33, t, x, make_float2(cc, ss));
    __syncthreads();
    cplx y[32];
    cplx* Sr = S + r * 1056;
    #pragma unroll
    for (int n2 = 0; n2 < 32; ++n2) y[n2] = Sr[t*33 + n2];
    dft32<-1>(y);
    __half2* o = g_Xh + (size_t)row * NN;
    #pragma unroll
    for (int k2 = 0; k2 < 32; ++k2) o[t + 32*k2] = c2h(y[k2]);
}

// rows_inv: reads ACC, re-zeroes it, writes D/1024 into g_Dh (half2)
__global__ __launch_bounds__(128) void k_rows_inv_acc() {
    __shared__ cplx S[4 * 1056];
    int tid = threadIdx.x;
    int r = tid >> 5, t = tid & 31;
    int row = blockIdx.x * 4 + r;
    cplx* src = ((cplx*)g_ACC) + (size_t)row * NN;
    cplx x[32];
    #pragma unroll
    for (int m = 0; m < 32; ++m) x[m] = src[m*32 + t];
    #pragma unroll
    for (int m = 0; m < 32; ++m) src[m*32 + t] = 0ULL;
    dft32<+1>(x);
    float ss, cc; sincospif((float)t / 512.0f, &ss, &cc);
    tw_store32(S + r * 1056, 33, t, x, make_float2(cc, ss));
    __syncthreads();
    cplx y[32];
    cplx* Sr = S + r * 1056;
    #pragma unroll
    for (int n2 = 0; n2 < 32; ++n2) y[n2] = Sr[t*33 + n2];
    dft32<+1>(y);
    __half2* o = g_Dh + (size_t)row * NN;
    const float dsc = 1.0f / 1024.0f;            // range-fold for half storage
    #pragma unroll
    for (int k2 = 0; k2 < 32; ++k2) {
        float a, bb; gxy(y[k2], a, bb);
        o[t + 32*k2] = __floats2half2_rn(a * dsc, bb * dsc);
    }
}

#define COLS_SMEM_BYTES (8 * 1058 * (int)sizeof(cplx))

__global__ __launch_bounds__(256) void k_cols_fwd_X() {
    extern __shared__ cplx S[];
    int tid = threadIdx.x;
    int c = tid & 7, t = tid >> 3;
    int b  = blockIdx.x >> 7;
    int c0 = (blockIdx.x & 127) * 8;
    __half2* img = g_Xh + (size_t)b * NN * NN;
    cplx x[32];
    #pragma unroll
    for (int m = 0; m < 32; ++m) x[m] = h2c(img[(size_t)(m*32 + t) * NN + c0 + c]);
    dft32<-1>(x);
    float ss, cc; sincospif(-(float)t / 512.0f, &ss, &cc);
    tw_store32(S + c * 1058, 33, t, x, make_float2(cc, ss));
    __syncthreads();
    cplx y[32];
    cplx* Sc = S + c * 1058;
    #pragma unroll
    for (int n2 = 0; n2 < 32; ++n2) y[n2] = Sc[t*33 + n2];
    dft32<-1>(y);
    #pragma unroll
    for (int k2 = 0; k2 < 32; ++k2) img[(size_t)(t + 32*k2) * NN + c0 + c] = c2h(y[k2]);
}

__global__ __launch_bounds__(256) void k_cols_inv_final(const float* __restrict__ img_a, const float* __restrict__ xre,
                                 const float* __restrict__ xim,  const float* __restrict__ lamb,
                                 const float* __restrict__ eta1, float* __restrict__ out,
                                 long long out_size) {
    extern __shared__ cplx S[];
    int tid = threadIdx.x;
    int c = tid & 7, t = tid >> 3;
    int b  = blockIdx.x >> 7;
    int c0 = (blockIdx.x & 127) * 8;
    const __half2* img = g_Dh + (size_t)b * NN * NN;
    cplx x[32];
    #pragma unroll
    for (int m = 0; m < 32; ++m) x[m] = h2c(img[(size_t)(m*32 + t) * NN + c0 + c]);
    dft32<+1>(x);
    float ss, cc; sincospif((float)t / 512.0f, &ss, &cc);
    tw_store32(S + c * 1058, 33, t, x, make_float2(cc, ss));
    __syncthreads();
    cplx y[32];
    cplx* Sc = S + c * 1058;
    #pragma unroll
    for (int n2 = 0; n2 < 32; ++n2) y[n2] = Sc[t*33 + n2];
    dft32<+1>(y);
    float e1  = eta1[0];
    float lm  = lamb[0];
    float bco = 100.0f * e1 * lm;
    float aco = 10.0f  * e1;
    // D stored pre-scaled by 1/1024: needed aco/(L*2^20) * 1024 = aco/(L*1024)
    float coef = aco / ((float)LL * 1024.0f);
    float one_m_b = 1.0f - bco;
    #pragma unroll
    for (int k2 = 0; k2 < 32; ++k2) {
        int rrow = t + 32*k2;
        long long idx = ((long long)b * NN + rrow) * NN + c0 + c;
        float dx, dy; gxy(y[k2], dx, dy);
        float xr = xre[idx], xi = xim[idx];
        float m  = sqrtf(fmaf(xr, xr, xi * xi)) + 1e-6f;
        float fa = bco * img_a[idx] / m;
        float rcx = one_m_b * xr - coef * dx + fa * xr;
        float rcy = one_m_b * xi - coef * dy + fa * xi;
        if (idx < out_size) out[idx] = sqrtf(fmaf(rcx, rcx, rcy * rcy));
        long long ore = (long long)IMG_PIX + idx;
        long long oim = (long long)(2 * IMG_PIX) + idx;
        if (ore < out_size) out[ore] = rcx;
        if (oim < out_size) out[oim] = rcy;
    }
}

// ================= patch kernels (half2 intermediates) =================

__global__ __launch_bounds__(256) void k_p1(const int* __restrict__ masks, const float* __restrict__ ctf) {
    __shared__ cplx S[16 * 272];
    int tid = threadIdx.x;
    int r = tid >> 4, t = tid & 15;
    int rg = blockIdx.x & 15;
    int pk = blockIdx.x >> 4;
    int b  = pk >> 6, k = pk & 63;
    int mr = masks[2*k] - 1, mc = masks[2*k+1] - 1;
    int i  = (rg << 4) + r;
    int gr = (mr + i + 512) & 1023;
    const __half2* Xrow = g_Xh + ((size_t)b * NN + gr) * NN;
    const float*  cfr  = ctf + i * NP;
    cplx x[16];
    const float sc = 1.0f / 256.0f;               // range-fold for half storage
    #pragma unroll
    for (int m = 0; m < 16; ++m) {
        int j  = m*16 + t;
        int gc = (mc + j + 512) & 1023;
        float2 v = __half22float2(Xrow[gc]);
        float cf = cfr[j] * sc;
        x[m] = mkc(v.x * cf, v.y * cf);
    }
    dft16<+1>(x);
    float ss, cc; sincospif(2.0f * (float)t / 256.0f, &ss, &cc);
    tw_store16(S + r * 272, 17, t, x, make_float2(cc, ss));
    __syncthreads();
    cplx y[16];
    cplx* Sr = S + r * 272;
    #pragma unroll
    for (int n2 = 0; n2 < 16; ++n2) y[n2] = Sr[t*17 + n2];
    dft16<+1>(y);
    __half2* o = g_S1h + ((size_t)pk * NP + i) * NP;
    #pragma unroll
    for (int k2 = 0; k2 < 16; ++k2) o[t + 16*k2] = c2h(y[k2]);
}

__global__ __launch_bounds__(256) void k_p2(const float* __restrict__ Y) {
    __shared__ cplx S[16 * 256];
    __shared__ float Ysm[256 * 16];
    int tid = threadIdx.x;
    int t = tid >> 4, c = tid & 15;
    int pk = blockIdx.x >> 4;
    int c0 = (blockIdx.x & 15) << 4;
    // prefetch Y tile (coalesced; first sync covers it)
    const float* Yp = Y + (size_t)pk * NP * NP;
    #pragma unroll
    for (int q = 0; q < 16; ++q) {
        int idx = tid + q * 256;
        int row = idx >> 4, col = idx & 15;
        Ysm[idx] = Yp[row * NP + c0 + col];
    }
    __half2* P = g_S1h + (size_t)pk * NP * NP;
    cplx x[16];
    #pragma unroll
    for (int m = 0; m < 16; ++m) x[m] = h2c(P[(m*16 + t) * NP + c0 + c]);
    dft16<+1>(x);
    float ss, cc; sincospif(2.0f * (float)t / 256.0f, &ss, &cc);
    float2 w1inv = make_float2(cc, ss);
    tw_store16_p2(S, t, c, x, w1inv);
    __syncthreads();
    cplx y[16];
    #pragma unroll
    for (int n2 = 0; n2 < 16; ++n2) y[n2] = S[t*256 + n2*16 + c];
    dft16<+1>(y);
    const float inv = 1.0f / 256.0f;
    #pragma unroll
    for (int k2 = 0; k2 < 16; ++k2) {
        float wx, wy; gxy(y[k2], wx, wy);
        wx *= inv; wy *= inv;
        float mag2 = fmaf(wx, wx, wy * wy);
        float yv   = Ysm[(t + 16*k2) * 16 + c];
        if (mag2 > 0.0f) {
            float f = 1.0f - sqrtf(__fdividef(yv, mag2));
            y[k2] = mkc(wx * f, wy * f);
        } else {
            y[k2] = mkc(-sqrtf(yv), 0.0f);
        }
    }
    dft16<-1>(y);
    __syncthreads();
    tw_store16_p2(S, t, c, y, conjf2(w1inv));
    __syncthreads();
    cplx z[16];
    #pragma unroll
    for (int n2 = 0; n2 < 16; ++n2) z[n2] = S[t*256 + n2*16 + c];
    dft16<-1>(z);
    #pragma unroll
    for (int k2 = 0; k2 < 16; ++k2) P[(t + 16*k2) * NP + c0 + c] = c2h(z[k2]);
}

__global__ __launch_bounds__(256) void k_p3(const int* __restrict__ masks, const float* __restrict__ ctf) {
    __shared__ cplx S[16 * 272];
    int tid = threadIdx.x;
    int r = tid >> 4, t = tid & 15;
    int rg = blockIdx.x & 15;
    int pk = blockIdx.x >> 4;
    int b  = pk >> 6, k = pk & 63;
    int mr = masks[2*k] - 1, mc = masks[2*k+1] - 1;
    int i  = (rg << 4) + r;
    const __half2* src = g_S1h + ((size_t)pk * NP + i) * NP;
    cplx x[16];
    #pragma unroll
    for (int m = 0; m < 16; ++m) x[m] = h2c(src[m*16 + t]);
    dft16<-1>(x);
    float ss, cc; sincospif(-2.0f * (float)t / 256.0f, &ss, &cc);
    tw_store16(S + r * 272, 17, t, x, make_float2(cc, ss));
    __syncthreads();
    cplx y[16];
    cplx* Sr = S + r * 272;
    #pragma unroll
    for (int n2 = 0; n2 < 16; ++n2) y[n2] = Sr[t*17 + n2];
    dft16<-1>(y);
    int gr = (mr + i + 512) & 1023;
    float* accrow = g_ACC + ((size_t)b * NN + gr) * NN * 2;
    const float* cfr = ctf + i * NP;
    #pragma unroll
    for (int k2 = 0; k2 < 16; ++k2) {
        int j  = t + 16*k2;
        float cf = cfr[j];
        float a, bb; gxy(y[k2], a, bb);
        int gc = (mc + j + 512) & 1023;
        red_add_v2(accrow + gc*2, a * cf, bb * cf);
    }
}

// ---------------- launch ----------------
extern "C" void kernel_launch(void* const* d_in, const int* in_sizes, int n_in,
                              void* d_out, int out_size) {
    const float* Img_a = (const float*)d_in[0];
    const float* Xre   = (const float*)d_in[1];
    const float* Xim   = (const float*)d_in[2];
    const float* Y     = (const float*)d_in[3];
    const int*   Masks = (const int*)  d_in[4];
    const float* CTF   = (const float*)d_in[5];
    const float* lamb  = (const float*)d_in[6];
    const float* eta1  = (const float*)d_in[7];
    float* out = (float*)d_out;

    cudaFuncSetAttribute((const void*)k_cols_fwd_X,
                         cudaFuncAttributeMaxDynamicSharedMemorySize, COLS_SMEM_BYTES);
    cudaFuncSetAttribute((const void*)k_cols_inv_final,
                         cudaFuncAttributeMaxDynamicSharedMemorySize, COLS_SMEM_BYTES);

    k_rows_fwd_planar<<<BATCH * NN / 4, 128>>>(Xre, Xim);
    k_cols_fwd_X<<<BATCH * 128, 256, COLS_SMEM_BYTES>>>();
    k_p1<<<BATCH * LL * 16, 256>>>(Masks, CTF);
    k_p2<<<BATCH * LL * 16, 256>>>(Y);
    k_p3<<<BATCH * LL * 16, 256>>>(Masks, CTF);
    k_rows_inv_acc<<<BATCH * NN / 4, 128>>>();
    k_cols_inv_final<<<BATCH * 128, 256, COLS_SMEM_BYTES>>>(
        Img_a, Xre, Xim, lamb, eta1, out, (long long)out_size);
}